// round 5
// baseline (speedup 1.0000x reference)
#include <cuda_runtime.h>
#include <cuda_fp16.h>
#include <cstdint>

#define SQ 2048
#define NBH 32
#define HD 128
#define BM 128
#define BN 64
#define PITCH 136        // half elements per smem row (128 + 8 pad) = 272B = 17*16B
#define TILEH (BN*PITCH) // halves per K or V tile buffer (8704)
#define NPAR 320         // 5 param arrays * 64 keys
#define SMEM_BYTES (4*TILEH*2 + 2*NPAR*4)   // 69632 + 2560 = 72192

// Persistent scratch (no cudaMalloc allowed)
__device__ __half g_q[SQ*NBH*HD];
__device__ __half g_k[SQ*NBH*HD];
__device__ __half g_v[SQ*NBH*HD];
__device__ float g_qsum[SQ*NBH];
__device__ float g_ksum[SQ*NBH];

// ---------------- prep: int32 codes -> fp16 (exact), plus row sums for q,k ----------------
__global__ void prep_kernel(const int* __restrict__ q, const int* __restrict__ k,
                            const int* __restrict__ v) {
    int warp = threadIdx.x >> 5, lane = threadIdx.x & 31;
    int row = blockIdx.x * 8 + warp;               // 0 .. S*BH-1
    int t = blockIdx.y;                            // 0=q, 1=k, 2=v
    const int* src = (t == 0) ? q : (t == 1) ? k : v;
    __half* dst = (t == 0) ? g_q : (t == 1) ? g_k : g_v;
    int4 c = *((const int4*)(src + (size_t)row * HD) + lane);
    __half2 p0 = __floats2half2_rn((float)c.x, (float)c.y);
    __half2 p1 = __floats2half2_rn((float)c.z, (float)c.w);
    uint2 w;
    w.x = *(unsigned*)&p0;
    w.y = *(unsigned*)&p1;
    *((uint2*)(dst + (size_t)row * HD) + lane) = w;
    if (t < 2) {
        int s = c.x + c.y + c.z + c.w;
        #pragma unroll
        for (int off = 16; off; off >>= 1) s += __shfl_xor_sync(0xffffffffu, s, off);
        if (lane == 0) ((t == 0) ? g_qsum : g_ksum)[row] = (float)s;
    }
}

__device__ __forceinline__ float ex2f(float x) {
    float y; asm("ex2.approx.f32 %0, %1;" : "=f"(y) : "f"(x)); return y;
}
__device__ __forceinline__ void cp16(void* dst, const void* src) {
    unsigned d = (unsigned)__cvta_generic_to_shared(dst);
    asm volatile("cp.async.cg.shared.global [%0], [%1], 16;" :: "r"(d), "l"(src));
}
__device__ __forceinline__ void cp4(void* dst, const void* src) {
    unsigned d = (unsigned)__cvta_generic_to_shared(dst);
    asm volatile("cp.async.ca.shared.global [%0], [%1], 4;" :: "r"(d), "l"(src));
}

#define MMA16816(cc, aa, b0v, b1v) \
    asm volatile("mma.sync.aligned.m16n8k16.row.col.f32.f16.f16.f32 " \
        "{%0,%1,%2,%3},{%4,%5,%6,%7},{%8,%9},{%0,%1,%2,%3};" \
        : "+f"(cc[0]), "+f"(cc[1]), "+f"(cc[2]), "+f"(cc[3]) \
        : "r"(aa[0]), "r"(aa[1]), "r"(aa[2]), "r"(aa[3]), "r"(b0v), "r"(b1v))

// ---------------- main: flash attention, BM=128 x full-D, BN=64 k-tiles, 2-stage cp.async ----------------
__global__ __launch_bounds__(256, 1) void attn_kernel(
    const float* __restrict__ qmin, const float* __restrict__ qscale,
    const float* __restrict__ kmin, const float* __restrict__ kscale,
    const float* __restrict__ vmin, const float* __restrict__ vscale,
    float* __restrict__ out)
{
    extern __shared__ __align__(16) unsigned char smem_raw[];
    __half* base = (__half*)smem_raw;
    __half* sKst[2] = { base,             base + 2*TILEH };
    __half* sVst[2] = { base + TILEH,     base + 3*TILEH };
    float*  sPst[2] = { (float*)(base + 4*TILEH), (float*)(base + 4*TILEH) + NPAR };
    __half* sQ = base;   // prologue-only: overlays stage-0 K+V (exactly 2*TILEH halves)

    const int tid = threadIdx.x, warp = tid >> 5, lane = tid & 31;
    const int g = lane >> 2, tg = lane & 3;
    const int bh = blockIdx.y, q0 = blockIdx.x * BM;

    // ---- stage Q tile to smem (fp16), then pull A-fragments into registers ----
    const __half* Qg = g_q + ((size_t)q0 * NBH + bh) * HD;
    #pragma unroll
    for (int i = 0; i < 16; i++) {
        int r = warp * 16 + i;
        uint2 w = *((const uint2*)(Qg + (size_t)r * NBH * HD) + lane);
        *((uint2*)(sQ + r * PITCH) + lane) = w;
    }
    __syncthreads();

    unsigned qf[8][4];
    const int r0 = warp * 16 + g, r1 = r0 + 8;
    #pragma unroll
    for (int kk = 0; kk < 8; kk++) {
        int c = kk * 16 + 2 * tg;
        qf[kk][0] = *(const unsigned*)(sQ + r0 * PITCH + c);
        qf[kk][1] = *(const unsigned*)(sQ + r1 * PITCH + c);
        qf[kk][2] = *(const unsigned*)(sQ + r0 * PITCH + c + 8);
        qf[kk][3] = *(const unsigned*)(sQ + r1 * PITCH + c + 8);
    }
    const size_t qi0 = (size_t)(q0 + r0) * NBH + bh, qi1 = qi0 + 8 * NBH;
    const float qa0 = qscale[qi0], qc0 = qmin[qi0];
    const float qB0 = qa0 * g_qsum[qi0] + 128.f * qc0;
    const float qa1 = qscale[qi1], qc1 = qmin[qi1];
    const float qB1 = qa1 * g_qsum[qi1] + 128.f * qc1;
    __syncthreads();   // done reading sQ: stage-0 buffers may now be overwritten

    // ---- cp.async tile issue: K/V as 16B chunks, params as 4B ----
    auto issue_tile = [&](int kb, int st) {
        const int kbase = kb * BN;
        const __half* Kg = g_k + ((size_t)kbase * NBH + bh) * HD;
        const __half* Vg = g_v + ((size_t)kbase * NBH + bh) * HD;
        __half* sK = sKst[st];
        __half* sV = sVst[st];
        #pragma unroll
        for (int j = 0; j < 4; j++) {
            int chunk = tid + j * 256;           // 0..1023
            int row = chunk >> 4, c16 = chunk & 15;
            cp16(sK + row * PITCH + c16 * 8, Kg + (size_t)row * NBH * HD + c16 * 8);
            cp16(sV + row * PITCH + c16 * 8, Vg + (size_t)row * NBH * HD + c16 * 8);
        }
        // params: [0:64) kscale [64:128) kmin [128:192) ksum [192:256) vscale [256:320) vmin
        {
            int arr = tid >> 6, key = tid & 63;
            const float* p = (arr == 0) ? kscale : (arr == 1) ? kmin : (arr == 2) ? g_ksum : vscale;
            cp4(sPst[st] + tid, p + (size_t)(kbase + key) * NBH + bh);
            if (tid < 64) cp4(sPst[st] + 256 + tid, vmin + (size_t)(kbase + tid) * NBH + bh);
        }
        asm volatile("cp.async.commit_group;" ::: "memory");
    };

    issue_tile(0, 0);

    float o[16][4];
    #pragma unroll
    for (int i = 0; i < 16; i++) { o[i][0] = o[i][1] = o[i][2] = o[i][3] = 0.f; }
    float m0 = -1e30f, m1 = -1e30f, l0 = 0.f, l1 = 0.f, bb0 = 0.f, bb1 = 0.f;
    const float SCL = 0.12752836805103852f;   // log2(e)/sqrt(128)

    for (int kb = 0; kb < SQ / BN; kb++) {
        const int st = kb & 1;
        if (kb + 1 < SQ / BN) {
            issue_tile(kb + 1, st ^ 1);   // overwrites buffer last read in kb-1 (fenced by end-of-body barrier)
            asm volatile("cp.async.wait_group 1;" ::: "memory");
        } else {
            asm volatile("cp.async.wait_group 0;" ::: "memory");
        }
        __syncthreads();   // tile kb visible to all warps

        __half* sK = sKst[st];
        const float* sP = sPst[st];
        const unsigned sVb = (unsigned)__cvta_generic_to_shared(sVst[st]);

        // ---- S = Q * K^T (exact in fp16: integer codes, fp32 accumulate) ----
        float c[8][4];
        #pragma unroll
        for (int i = 0; i < 8; i++) { c[i][0] = c[i][1] = c[i][2] = c[i][3] = 0.f; }
        #pragma unroll
        for (int kk = 0; kk < 8; kk++) {
            #pragma unroll
            for (int n8 = 0; n8 < 8; n8++) {
                const __half* kr = sK + (n8 * 8 + g) * PITCH + kk * 16 + 2 * tg;
                unsigned b0 = *(const unsigned*)(kr);
                unsigned b1 = *(const unsigned*)(kr + 8);
                MMA16816(c[n8], qf[kk], b0, b1);
            }
        }

        // ---- dequant corrections + online softmax ----
        float mx0 = -1e30f, mx1 = -1e30f;
        #pragma unroll
        for (int n8 = 0; n8 < 8; n8++) {
            int cc = n8 * 8 + 2 * tg;
            float al0 = sP[cc],            al1 = sP[cc + 1];
            float be0 = sP[64 + cc],       be1 = sP[64 + cc + 1];
            float ga0 = al0 * sP[128 + cc], ga1 = al1 * sP[128 + cc + 1];
            c[n8][0] = (qa0 * al0 * c[n8][0] + qB0 * be0 + qc0 * ga0) * SCL;
            c[n8][1] = (qa0 * al1 * c[n8][1] + qB0 * be1 + qc0 * ga1) * SCL;
            c[n8][2] = (qa1 * al0 * c[n8][2] + qB1 * be0 + qc1 * ga0) * SCL;
            c[n8][3] = (qa1 * al1 * c[n8][3] + qB1 * be1 + qc1 * ga1) * SCL;
            mx0 = fmaxf(mx0, fmaxf(c[n8][0], c[n8][1]));
            mx1 = fmaxf(mx1, fmaxf(c[n8][2], c[n8][3]));
        }
        mx0 = fmaxf(mx0, __shfl_xor_sync(~0u, mx0, 1));
        mx0 = fmaxf(mx0, __shfl_xor_sync(~0u, mx0, 2));
        mx1 = fmaxf(mx1, __shfl_xor_sync(~0u, mx1, 1));
        mx1 = fmaxf(mx1, __shfl_xor_sync(~0u, mx1, 2));
        const float mn0 = fmaxf(m0, mx0), mn1 = fmaxf(m1, mx1);
        const float cr0 = ex2f(m0 - mn0), cr1 = ex2f(m1 - mn1);
        m0 = mn0; m1 = mn1;

        unsigned pk[8][2];
        float pl0 = 0.f, pl1 = 0.f, pb0 = 0.f, pb1 = 0.f;
        #pragma unroll
        for (int n8 = 0; n8 < 8; n8++) {
            int cc = n8 * 8 + 2 * tg;
            float p00 = ex2f(c[n8][0] - mn0), p01 = ex2f(c[n8][1] - mn0);
            float p10 = ex2f(c[n8][2] - mn1), p11 = ex2f(c[n8][3] - mn1);
            pl0 += p00 + p01; pl1 += p10 + p11;
            float vs0 = sP[192 + cc], vs1 = sP[192 + cc + 1];
            float vm0 = sP[256 + cc], vm1 = sP[256 + cc + 1];
            pb0 += p00 * vm0 + p01 * vm1;
            pb1 += p10 * vm0 + p11 * vm1;
            __half2 t0 = __floats2half2_rn(p00 * vs0, p01 * vs1);
            __half2 t1 = __floats2half2_rn(p10 * vs0, p11 * vs1);
            pk[n8][0] = *(unsigned*)&t0;
            pk[n8][1] = *(unsigned*)&t1;
        }
        l0 = l0 * cr0 + pl0;  l1 = l1 * cr1 + pl1;
        bb0 = bb0 * cr0 + pb0; bb1 = bb1 * cr1 + pb1;
        #pragma unroll
        for (int i = 0; i < 16; i++) {
            o[i][0] *= cr0; o[i][1] *= cr0; o[i][2] *= cr1; o[i][3] *= cr1;
        }

        // ---- O += P' * Vcodes  (P' = p * vscale, fp16; V via ldmatrix.trans) ----
        #pragma unroll
        for (int kk = 0; kk < 4; kk++) {
            unsigned a[4] = { pk[2*kk][0], pk[2*kk][1], pk[2*kk+1][0], pk[2*kk+1][1] };
            #pragma unroll
            for (int nb = 0; nb < 8; nb++) {
                int rowl = kk * 16 + (lane & 15);
                int col  = nb * 16 + ((lane & 16) ? 8 : 0);
                unsigned addr = sVb + ((unsigned)(rowl * PITCH + col) << 1);
                unsigned v0, v1, v2, v3;
                asm volatile("ldmatrix.sync.aligned.m8n8.x4.trans.shared.b16 {%0,%1,%2,%3}, [%4];"
                             : "=r"(v0), "=r"(v1), "=r"(v2), "=r"(v3) : "r"(addr));
                MMA16816(o[2*nb],     a, v0, v1);
                MMA16816(o[2*nb + 1], a, v2, v3);
            }
        }
        __syncthreads();   // all reads of this stage done before it is re-filled at kb+1
    }

    // ---- epilogue: reduce l/bias across the quad, normalize, store fp32 ----
    l0  += __shfl_xor_sync(~0u, l0, 1);  l0  += __shfl_xor_sync(~0u, l0, 2);
    l1  += __shfl_xor_sync(~0u, l1, 1);  l1  += __shfl_xor_sync(~0u, l1, 2);
    bb0 += __shfl_xor_sync(~0u, bb0, 1); bb0 += __shfl_xor_sync(~0u, bb0, 2);
    bb1 += __shfl_xor_sync(~0u, bb1, 1); bb1 += __shfl_xor_sync(~0u, bb1, 2);
    const float iv0 = 1.f / l0, iv1 = 1.f / l1;
    float* O0 = out + (size_t)(q0 + r0) * NBH * HD + (size_t)bh * HD;
    float* O1 = out + (size_t)(q0 + r1) * NBH * HD + (size_t)bh * HD;
    #pragma unroll
    for (int i = 0; i < 16; i++) {
        int d0 = i * 8 + 2 * tg;
        float2 w0 = make_float2((o[i][0] + bb0) * iv0, (o[i][1] + bb0) * iv0);
        float2 w1 = make_float2((o[i][2] + bb1) * iv1, (o[i][3] + bb1) * iv1);
        *(float2*)(O0 + d0) = w0;
        *(float2*)(O1 + d0) = w1;
    }
}

extern "C" void kernel_launch(void* const* d_in, const int* in_sizes, int n_in,
                              void* d_out, int out_size) {
    const int*   q      = (const int*)d_in[0];
    const int*   k      = (const int*)d_in[1];
    const int*   v      = (const int*)d_in[2];
    const float* qmn    = (const float*)d_in[3];
    const float* qsc    = (const float*)d_in[4];
    const float* kmn    = (const float*)d_in[5];
    const float* ksc    = (const float*)d_in[6];
    const float* vmn    = (const float*)d_in[7];
    const float* vsc    = (const float*)d_in[8];

    (void)cudaFuncSetAttribute(attn_kernel, cudaFuncAttributeMaxDynamicSharedMemorySize, SMEM_BYTES);

    dim3 pg(SQ * NBH / 8, 3);
    prep_kernel<<<pg, 256>>>(q, k, v);

    dim3 ag(SQ / BM, NBH);   // qtile fastest -> concurrent CTAs share a head's K/V in L2
    attn_kernel<<<ag, 256, SMEM_BYTES>>>(qmn, qsc, kmn, ksc, vmn, vsc, (float*)d_out);
}

// round 6
// speedup vs baseline: 1.0756x; 1.0756x over previous
#include <cuda_runtime.h>
#include <cuda_fp16.h>
#include <cstdint>

#define SQ 2048
#define NBH 32
#define HD 128
#define BM 64            // q rows per CTA (4 warps x 16 rows)
#define BN 64
#define NTHREADS 128
#define PITCH 136        // half elements per smem row (128 + 8 pad) = 272B
#define TILEH (BN*PITCH) // halves per K or V tile buffer (8704)
#define NPAR 320         // 5 param arrays * 64 keys
#define SMEM_BYTES (4*TILEH*2 + 2*NPAR*4)   // 69632 + 2560 = 72192

// Persistent scratch (no cudaMalloc allowed)
__device__ __half g_q[SQ*NBH*HD];
__device__ __half g_k[SQ*NBH*HD];
__device__ __half g_v[SQ*NBH*HD];
__device__ float g_qsum[SQ*NBH];
__device__ float g_ksum[SQ*NBH];

// ---------------- prep: int32 codes -> fp16 (exact), plus row sums for q,k ----------------
__global__ void prep_kernel(const int* __restrict__ q, const int* __restrict__ k,
                            const int* __restrict__ v) {
    int warp = threadIdx.x >> 5, lane = threadIdx.x & 31;
    int row = blockIdx.x * 8 + warp;               // 0 .. S*BH-1
    int t = blockIdx.y;                            // 0=q, 1=k, 2=v
    const int* src = (t == 0) ? q : (t == 1) ? k : v;
    __half* dst = (t == 0) ? g_q : (t == 1) ? g_k : g_v;
    int4 c = *((const int4*)(src + (size_t)row * HD) + lane);
    __half2 p0 = __floats2half2_rn((float)c.x, (float)c.y);
    __half2 p1 = __floats2half2_rn((float)c.z, (float)c.w);
    uint2 w;
    w.x = *(unsigned*)&p0;
    w.y = *(unsigned*)&p1;
    *((uint2*)(dst + (size_t)row * HD) + lane) = w;
    if (t < 2) {
        int s = c.x + c.y + c.z + c.w;
        #pragma unroll
        for (int off = 16; off; off >>= 1) s += __shfl_xor_sync(0xffffffffu, s, off);
        if (lane == 0) ((t == 0) ? g_qsum : g_ksum)[row] = (float)s;
    }
}

__device__ __forceinline__ float ex2f(float x) {
    float y; asm("ex2.approx.f32 %0, %1;" : "=f"(y) : "f"(x)); return y;
}
__device__ __forceinline__ void cp16(void* dst, const void* src) {
    unsigned d = (unsigned)__cvta_generic_to_shared(dst);
    asm volatile("cp.async.cg.shared.global [%0], [%1], 16;" :: "r"(d), "l"(src));
}
__device__ __forceinline__ void cp4(void* dst, const void* src) {
    unsigned d = (unsigned)__cvta_generic_to_shared(dst);
    asm volatile("cp.async.ca.shared.global [%0], [%1], 4;" :: "r"(d), "l"(src));
}

#define MMA16816(cc, aa, b0v, b1v) \
    asm volatile("mma.sync.aligned.m16n8k16.row.col.f32.f16.f16.f32 " \
        "{%0,%1,%2,%3},{%4,%5,%6,%7},{%8,%9},{%0,%1,%2,%3};" \
        : "+f"(cc[0]), "+f"(cc[1]), "+f"(cc[2]), "+f"(cc[3]) \
        : "r"(aa[0]), "r"(aa[1]), "r"(aa[2]), "r"(aa[3]), "r"(b0v), "r"(b1v))

// ---------------- main: flash attention, BM=64 x full-D, BN=64 k-tiles, 2-stage cp.async ----------------
__global__ __launch_bounds__(NTHREADS, 2) void attn_kernel(
    const float* __restrict__ qmin, const float* __restrict__ qscale,
    const float* __restrict__ kmin, const float* __restrict__ kscale,
    const float* __restrict__ vmin, const float* __restrict__ vscale,
    float* __restrict__ out)
{
    extern __shared__ __align__(16) unsigned char smem_raw[];
    __half* base = (__half*)smem_raw;
    __half* sKst[2] = { base,             base + 2*TILEH };
    __half* sVst[2] = { base + TILEH,     base + 3*TILEH };
    float*  sPst[2] = { (float*)(base + 4*TILEH), (float*)(base + 4*TILEH) + NPAR };
    __half* sQ = base;   // prologue-only: overlays stage-0 K (exactly TILEH halves: 64*PITCH)

    const int tid = threadIdx.x, warp = tid >> 5, lane = tid & 31;
    const int g = lane >> 2, tg = lane & 3;
    const int bh = blockIdx.y, q0 = blockIdx.x * BM;

    // ---- stage Q tile to smem (fp16), then pull A-fragments into registers ----
    const __half* Qg = g_q + ((size_t)q0 * NBH + bh) * HD;
    #pragma unroll
    for (int i = 0; i < 16; i++) {
        int r = warp * 16 + i;
        uint2 w = *((const uint2*)(Qg + (size_t)r * NBH * HD) + lane);
        *((uint2*)(sQ + r * PITCH) + lane) = w;
    }
    __syncthreads();

    unsigned qf[8][4];
    const int r0 = warp * 16 + g, r1 = r0 + 8;
    #pragma unroll
    for (int kk = 0; kk < 8; kk++) {
        int c = kk * 16 + 2 * tg;
        qf[kk][0] = *(const unsigned*)(sQ + r0 * PITCH + c);
        qf[kk][1] = *(const unsigned*)(sQ + r1 * PITCH + c);
        qf[kk][2] = *(const unsigned*)(sQ + r0 * PITCH + c + 8);
        qf[kk][3] = *(const unsigned*)(sQ + r1 * PITCH + c + 8);
    }
    const size_t qi0 = (size_t)(q0 + r0) * NBH + bh, qi1 = qi0 + 8 * NBH;
    const float qa0 = qscale[qi0], qc0 = qmin[qi0];
    const float qB0 = qa0 * g_qsum[qi0] + 128.f * qc0;
    const float qa1 = qscale[qi1], qc1 = qmin[qi1];
    const float qB1 = qa1 * g_qsum[qi1] + 128.f * qc1;
    __syncthreads();   // done reading sQ: stage-0 buffers may now be overwritten

    // ---- cp.async tile issue: K/V as 16B chunks, params as 4B ----
    auto issue_tile = [&](int kb, int st) {
        const int kbase = kb * BN;
        const __half* Kg = g_k + ((size_t)kbase * NBH + bh) * HD;
        const __half* Vg = g_v + ((size_t)kbase * NBH + bh) * HD;
        __half* sK = sKst[st];
        __half* sV = sVst[st];
        #pragma unroll
        for (int j = 0; j < 8; j++) {
            int chunk = tid + j * NTHREADS;      // 0..1023
            int row = chunk >> 4, c16 = chunk & 15;
            cp16(sK + row * PITCH + c16 * 8, Kg + (size_t)row * NBH * HD + c16 * 8);
            cp16(sV + row * PITCH + c16 * 8, Vg + (size_t)row * NBH * HD + c16 * 8);
        }
        // params: [0:64) kscale [64:128) kmin [128:192) ksum [192:256) vscale [256:320) vmin
        #pragma unroll
        for (int i = tid; i < NPAR; i += NTHREADS) {
            int arr = i >> 6, key = i & 63;
            const float* p = (arr == 0) ? kscale : (arr == 1) ? kmin :
                             (arr == 2) ? g_ksum : (arr == 3) ? vscale : vmin;
            cp4(sPst[st] + i, p + (size_t)(kbase + key) * NBH + bh);
        }
        asm volatile("cp.async.commit_group;" ::: "memory");
    };

    issue_tile(0, 0);

    float o[16][4];
    #pragma unroll
    for (int i = 0; i < 16; i++) { o[i][0] = o[i][1] = o[i][2] = o[i][3] = 0.f; }
    float m0 = -1e30f, m1 = -1e30f, l0 = 0.f, l1 = 0.f, bb0 = 0.f, bb1 = 0.f;
    const float SCL = 0.12752836805103852f;   // log2(e)/sqrt(128)

    for (int kb = 0; kb < SQ / BN; kb++) {
        const int st = kb & 1;
        if (kb + 1 < SQ / BN) {
            issue_tile(kb + 1, st ^ 1);   // overwrites buffer last read in kb-1 (fenced by end-of-body barrier)
            asm volatile("cp.async.wait_group 1;" ::: "memory");
        } else {
            asm volatile("cp.async.wait_group 0;" ::: "memory");
        }
        __syncthreads();   // tile kb visible to all warps

        const float* sP = sPst[st];
        const unsigned sKb = (unsigned)__cvta_generic_to_shared(sKst[st]);
        const unsigned sVb = (unsigned)__cvta_generic_to_shared(sVst[st]);

        // ---- S = Q * K^T (exact in fp16: integer codes, fp32 accumulate) ----
        float c[8][4];
        #pragma unroll
        for (int i = 0; i < 8; i++) { c[i][0] = c[i][1] = c[i][2] = c[i][3] = 0.f; }
        // K B-fragments via ldmatrix.x4: one load covers two n8 blocks at one kk
        const int krow_in = (lane & 7) + ((lane & 16) ? 8 : 0);
        const int kcol_in = (lane & 8) ? 8 : 0;
        #pragma unroll
        for (int kk = 0; kk < 8; kk++) {
            #pragma unroll
            for (int np = 0; np < 4; np++) {
                unsigned addr = sKb + ((unsigned)((np * 16 + krow_in) * PITCH + kk * 16 + kcol_in) << 1);
                unsigned v0, v1, v2, v3;
                asm volatile("ldmatrix.sync.aligned.m8n8.x4.shared.b16 {%0,%1,%2,%3}, [%4];"
                             : "=r"(v0), "=r"(v1), "=r"(v2), "=r"(v3) : "r"(addr));
                MMA16816(c[2*np],     qf[kk], v0, v1);
                MMA16816(c[2*np + 1], qf[kk], v2, v3);
            }
        }

        // ---- dequant corrections + online softmax ----
        float mx0 = -1e30f, mx1 = -1e30f;
        #pragma unroll
        for (int n8 = 0; n8 < 8; n8++) {
            int cc = n8 * 8 + 2 * tg;
            float al0 = sP[cc],            al1 = sP[cc + 1];
            float be0 = sP[64 + cc],       be1 = sP[64 + cc + 1];
            float ga0 = al0 * sP[128 + cc], ga1 = al1 * sP[128 + cc + 1];
            c[n8][0] = (qa0 * al0 * c[n8][0] + qB0 * be0 + qc0 * ga0) * SCL;
            c[n8][1] = (qa0 * al1 * c[n8][1] + qB0 * be1 + qc0 * ga1) * SCL;
            c[n8][2] = (qa1 * al0 * c[n8][2] + qB1 * be0 + qc1 * ga0) * SCL;
            c[n8][3] = (qa1 * al1 * c[n8][3] + qB1 * be1 + qc1 * ga1) * SCL;
            mx0 = fmaxf(mx0, fmaxf(c[n8][0], c[n8][1]));
            mx1 = fmaxf(mx1, fmaxf(c[n8][2], c[n8][3]));
        }
        mx0 = fmaxf(mx0, __shfl_xor_sync(~0u, mx0, 1));
        mx0 = fmaxf(mx0, __shfl_xor_sync(~0u, mx0, 2));
        mx1 = fmaxf(mx1, __shfl_xor_sync(~0u, mx1, 1));
        mx1 = fmaxf(mx1, __shfl_xor_sync(~0u, mx1, 2));
        const float mn0 = fmaxf(m0, mx0), mn1 = fmaxf(m1, mx1);
        const bool nochange = (m0 == mn0) & (m1 == mn1);
        const float cr0 = ex2f(m0 - mn0), cr1 = ex2f(m1 - mn1);
        m0 = mn0; m1 = mn1;

        unsigned pk[8][2];
        float pl0 = 0.f, pl1 = 0.f, pb0 = 0.f, pb1 = 0.f;
        #pragma unroll
        for (int n8 = 0; n8 < 8; n8++) {
            int cc = n8 * 8 + 2 * tg;
            float p00 = ex2f(c[n8][0] - mn0), p01 = ex2f(c[n8][1] - mn0);
            float p10 = ex2f(c[n8][2] - mn1), p11 = ex2f(c[n8][3] - mn1);
            pl0 += p00 + p01; pl1 += p10 + p11;
            float vs0 = sP[192 + cc], vs1 = sP[192 + cc + 1];
            float vm0 = sP[256 + cc], vm1 = sP[256 + cc + 1];
            pb0 += p00 * vm0 + p01 * vm1;
            pb1 += p10 * vm0 + p11 * vm1;
            __half2 t0 = __floats2half2_rn(p00 * vs0, p01 * vs1);
            __half2 t1 = __floats2half2_rn(p10 * vs0, p11 * vs1);
            pk[n8][0] = *(unsigned*)&t0;
            pk[n8][1] = *(unsigned*)&t1;
        }
        l0 = l0 * cr0 + pl0;  l1 = l1 * cr1 + pl1;
        bb0 = bb0 * cr0 + pb0; bb1 = bb1 * cr1 + pb1;
        if (!__all_sync(0xffffffffu, nochange)) {
            #pragma unroll
            for (int i = 0; i < 16; i++) {
                o[i][0] *= cr0; o[i][1] *= cr0; o[i][2] *= cr1; o[i][3] *= cr1;
            }
        }

        // ---- O += P' * Vcodes  (P' = p * vscale, fp16; V via ldmatrix.trans) ----
        #pragma unroll
        for (int kk = 0; kk < 4; kk++) {
            unsigned a[4] = { pk[2*kk][0], pk[2*kk][1], pk[2*kk+1][0], pk[2*kk+1][1] };
            #pragma unroll
            for (int nb = 0; nb < 8; nb++) {
                int rowl = kk * 16 + (lane & 15);
                int col  = nb * 16 + ((lane & 16) ? 8 : 0);
                unsigned addr = sVb + ((unsigned)(rowl * PITCH + col) << 1);
                unsigned v0, v1, v2, v3;
                asm volatile("ldmatrix.sync.aligned.m8n8.x4.trans.shared.b16 {%0,%1,%2,%3}, [%4];"
                             : "=r"(v0), "=r"(v1), "=r"(v2), "=r"(v3) : "r"(addr));
                MMA16816(o[2*nb],     a, v0, v1);
                MMA16816(o[2*nb + 1], a, v2, v3);
            }
        }
        __syncthreads();   // all reads of this stage done before it is re-filled at kb+1
    }

    // ---- epilogue: reduce l/bias across the quad, normalize, store fp32 ----
    l0  += __shfl_xor_sync(~0u, l0, 1);  l0  += __shfl_xor_sync(~0u, l0, 2);
    l1  += __shfl_xor_sync(~0u, l1, 1);  l1  += __shfl_xor_sync(~0u, l1, 2);
    bb0 += __shfl_xor_sync(~0u, bb0, 1); bb0 += __shfl_xor_sync(~0u, bb0, 2);
    bb1 += __shfl_xor_sync(~0u, bb1, 1); bb1 += __shfl_xor_sync(~0u, bb1, 2);
    const float iv0 = 1.f / l0, iv1 = 1.f / l1;
    float* O0 = out + (size_t)(q0 + r0) * NBH * HD + (size_t)bh * HD;
    float* O1 = out + (size_t)(q0 + r1) * NBH * HD + (size_t)bh * HD;
    #pragma unroll
    for (int i = 0; i < 16; i++) {
        int d0 = i * 8 + 2 * tg;
        float2 w0 = make_float2((o[i][0] + bb0) * iv0, (o[i][1] + bb0) * iv0);
        float2 w1 = make_float2((o[i][2] + bb1) * iv1, (o[i][3] + bb1) * iv1);
        *(float2*)(O0 + d0) = w0;
        *(float2*)(O1 + d0) = w1;
    }
}

extern "C" void kernel_launch(void* const* d_in, const int* in_sizes, int n_in,
                              void* d_out, int out_size) {
    const int*   q      = (const int*)d_in[0];
    const int*   k      = (const int*)d_in[1];
    const int*   v      = (const int*)d_in[2];
    const float* qmn    = (const float*)d_in[3];
    const float* qsc    = (const float*)d_in[4];
    const float* kmn    = (const float*)d_in[5];
    const float* ksc    = (const float*)d_in[6];
    const float* vmn    = (const float*)d_in[7];
    const float* vsc    = (const float*)d_in[8];

    (void)cudaFuncSetAttribute(attn_kernel, cudaFuncAttributeMaxDynamicSharedMemorySize, SMEM_BYTES);

    dim3 pg(SQ * NBH / 8, 3);
    prep_kernel<<<pg, 256>>>(q, k, v);

    dim3 ag(SQ / BM, NBH);   // qtile fastest -> concurrent CTAs share a head's K/V in L2
    attn_kernel<<<ag, NTHREADS, SMEM_BYTES>>>(qmn, qsc, kmn, ksc, vmn, vsc, (float*)d_out);
}

// round 7
// speedup vs baseline: 1.0941x; 1.0172x over previous
#include <cuda_runtime.h>
#include <cuda_fp16.h>
#include <cstdint>

#define SQ 2048
#define NBH 32
#define HD 128
#define BM 64            // q rows per CTA (4 warps x 16 rows)
#define BN 64
#define NTHREADS 128
#define PITCH 136        // half elements per smem row (128 + 8 pad) = 272B
#define TILEH (BN*PITCH) // halves per K or V tile buffer (8704)
#define PARBYTES (64*16 + 64*4)             // float4 per key + vmin per key = 1280
#define SMEM_BYTES (4*TILEH*2 + 2*PARBYTES) // 69632 + 2560 = 72192

// Persistent scratch (no cudaMalloc allowed)
__device__ __half g_q[SQ*NBH*HD];
__device__ __half g_k[SQ*NBH*HD];
__device__ __half g_v[SQ*NBH*HD];
__device__ float g_qsum[SQ*NBH];
__device__ float4 g_kpar[SQ*NBH];   // (kscale, kmin, kscale*ksum, vscale)

// ---------------- prep: int32 codes -> fp16 (exact), q row sums, packed k params ----------------
__global__ void prep_kernel(const int* __restrict__ q, const int* __restrict__ k,
                            const int* __restrict__ v,
                            const float* __restrict__ kmin, const float* __restrict__ kscale,
                            const float* __restrict__ vscale) {
    int warp = threadIdx.x >> 5, lane = threadIdx.x & 31;
    int row = blockIdx.x * 8 + warp;               // 0 .. S*BH-1
    int t = blockIdx.y;                            // 0=q, 1=k, 2=v
    const int* src = (t == 0) ? q : (t == 1) ? k : v;
    __half* dst = (t == 0) ? g_q : (t == 1) ? g_k : g_v;
    int4 c = *((const int4*)(src + (size_t)row * HD) + lane);
    __half2 p0 = __floats2half2_rn((float)c.x, (float)c.y);
    __half2 p1 = __floats2half2_rn((float)c.z, (float)c.w);
    uint2 w;
    w.x = *(unsigned*)&p0;
    w.y = *(unsigned*)&p1;
    *((uint2*)(dst + (size_t)row * HD) + lane) = w;
    if (t < 2) {
        int s = c.x + c.y + c.z + c.w;
        #pragma unroll
        for (int off = 16; off; off >>= 1) s += __shfl_xor_sync(0xffffffffu, s, off);
        if (lane == 0) {
            if (t == 0) {
                g_qsum[row] = (float)s;
            } else {
                float ks = kscale[row];
                g_kpar[row] = make_float4(ks, kmin[row], ks * (float)s, vscale[row]);
            }
        }
    }
}

__device__ __forceinline__ float ex2f(float x) {
    float y; asm("ex2.approx.f32 %0, %1;" : "=f"(y) : "f"(x)); return y;
}
__device__ __forceinline__ void cp16(void* dst, const void* src) {
    unsigned d = (unsigned)__cvta_generic_to_shared(dst);
    asm volatile("cp.async.cg.shared.global [%0], [%1], 16;" :: "r"(d), "l"(src));
}
__device__ __forceinline__ void cp4(void* dst, const void* src) {
    unsigned d = (unsigned)__cvta_generic_to_shared(dst);
    asm volatile("cp.async.ca.shared.global [%0], [%1], 4;" :: "r"(d), "l"(src));
}

#define MMA16816(cc, aa, b0v, b1v) \
    asm volatile("mma.sync.aligned.m16n8k16.row.col.f32.f16.f16.f32 " \
        "{%0,%1,%2,%3},{%4,%5,%6,%7},{%8,%9},{%0,%1,%2,%3};" \
        : "+f"(cc[0]), "+f"(cc[1]), "+f"(cc[2]), "+f"(cc[3]) \
        : "r"(aa[0]), "r"(aa[1]), "r"(aa[2]), "r"(aa[3]), "r"(b0v), "r"(b1v))

// ---------------- main: flash attention, BM=64 x full-D, BN=64 k-tiles, 2-stage cp.async ----------------
__global__ __launch_bounds__(NTHREADS, 3) void attn_kernel(
    const float* __restrict__ qmin, const float* __restrict__ qscale,
    const float* __restrict__ vmin,
    float* __restrict__ out)
{
    extern __shared__ __align__(16) unsigned char smem_raw[];
    __half* base = (__half*)smem_raw;
    __half* sKst[2] = { base,             base + 2*TILEH };
    __half* sVst[2] = { base + TILEH,     base + 3*TILEH };
    float4* sP4st[2] = { (float4*)(base + 4*TILEH),
                         (float4*)((unsigned char*)(base + 4*TILEH) + PARBYTES) };
    float*  sVmst[2] = { (float*)(sP4st[0] + 64), (float*)(sP4st[1] + 64) };
    __half* sQ = base;   // prologue-only: overlays stage-0 K (exactly TILEH halves)

    const int tid = threadIdx.x, warp = tid >> 5, lane = tid & 31;
    const int g = lane >> 2, tg = lane & 3;
    const int bh = blockIdx.y, q0 = blockIdx.x * BM;

    // ---- stage Q tile to smem (fp16), then pull A-fragments into registers ----
    const __half* Qg = g_q + ((size_t)q0 * NBH + bh) * HD;
    #pragma unroll
    for (int i = 0; i < 16; i++) {
        int r = warp * 16 + i;
        uint2 w = *((const uint2*)(Qg + (size_t)r * NBH * HD) + lane);
        *((uint2*)(sQ + r * PITCH) + lane) = w;
    }
    __syncthreads();

    unsigned qf[8][4];
    const int r0 = warp * 16 + g, r1 = r0 + 8;
    #pragma unroll
    for (int kk = 0; kk < 8; kk++) {
        int c = kk * 16 + 2 * tg;
        qf[kk][0] = *(const unsigned*)(sQ + r0 * PITCH + c);
        qf[kk][1] = *(const unsigned*)(sQ + r1 * PITCH + c);
        qf[kk][2] = *(const unsigned*)(sQ + r0 * PITCH + c + 8);
        qf[kk][3] = *(const unsigned*)(sQ + r1 * PITCH + c + 8);
    }
    const size_t qi0 = (size_t)(q0 + r0) * NBH + bh, qi1 = qi0 + 8 * NBH;
    const float qa0 = qscale[qi0], qc0 = qmin[qi0];
    const float qB0 = qa0 * g_qsum[qi0] + 128.f * qc0;
    const float qa1 = qscale[qi1], qc1 = qmin[qi1];
    const float qB1 = qa1 * g_qsum[qi1] + 128.f * qc1;
    __syncthreads();   // done reading sQ: stage-0 buffers may now be overwritten

    // ---- cp.async tile issue: K/V as 16B chunks, packed params ----
    auto issue_tile = [&](int kb, int st) {
        const int kbase = kb * BN;
        const __half* Kg = g_k + ((size_t)kbase * NBH + bh) * HD;
        const __half* Vg = g_v + ((size_t)kbase * NBH + bh) * HD;
        __half* sK = sKst[st];
        __half* sV = sVst[st];
        #pragma unroll
        for (int j = 0; j < 8; j++) {
            int chunk = tid + j * NTHREADS;      // 0..1023
            int row = chunk >> 4, c16 = chunk & 15;
            cp16(sK + row * PITCH + c16 * 8, Kg + (size_t)row * NBH * HD + c16 * 8);
            cp16(sV + row * PITCH + c16 * 8, Vg + (size_t)row * NBH * HD + c16 * 8);
        }
        if (tid < 64) {
            cp16(sP4st[st] + tid, g_kpar + (size_t)(kbase + tid) * NBH + bh);
        } else {
            int key = tid - 64;
            cp4(sVmst[st] + key, vmin + (size_t)(kbase + key) * NBH + bh);
        }
        asm volatile("cp.async.commit_group;" ::: "memory");
    };

    issue_tile(0, 0);

    float o[16][4];
    #pragma unroll
    for (int i = 0; i < 16; i++) { o[i][0] = o[i][1] = o[i][2] = o[i][3] = 0.f; }
    float m0 = -1e30f, m1 = -1e30f, l0 = 0.f, l1 = 0.f, bb0 = 0.f, bb1 = 0.f;
    const float SCL = 0.12752836805103852f;   // log2(e)/sqrt(128)

    for (int kb = 0; kb < SQ / BN; kb++) {
        const int st = kb & 1;
        if (kb + 1 < SQ / BN) {
            issue_tile(kb + 1, st ^ 1);   // overwrites buffer last read in kb-1 (fenced by end-of-body barrier)
            asm volatile("cp.async.wait_group 1;" ::: "memory");
        } else {
            asm volatile("cp.async.wait_group 0;" ::: "memory");
        }
        __syncthreads();   // tile kb visible to all warps

        const float4* sP4 = sP4st[st];
        const float* sVm = sVmst[st];
        const unsigned sKb = (unsigned)__cvta_generic_to_shared(sKst[st]);
        const unsigned sVb = (unsigned)__cvta_generic_to_shared(sVst[st]);

        // ---- S = Q * K^T (exact in fp16: integer codes, fp32 accumulate) ----
        float c[8][4];
        #pragma unroll
        for (int i = 0; i < 8; i++) { c[i][0] = c[i][1] = c[i][2] = c[i][3] = 0.f; }
        // K B-fragments via ldmatrix.x4: one load covers two n8 blocks at one kk
        const int krow_in = (lane & 7) + ((lane & 16) ? 8 : 0);
        const int kcol_in = (lane & 8) ? 8 : 0;
        #pragma unroll
        for (int kk = 0; kk < 8; kk++) {
            #pragma unroll
            for (int np = 0; np < 4; np++) {
                unsigned addr = sKb + ((unsigned)((np * 16 + krow_in) * PITCH + kk * 16 + kcol_in) << 1);
                unsigned v0, v1, v2, v3;
                asm volatile("ldmatrix.sync.aligned.m8n8.x4.shared.b16 {%0,%1,%2,%3}, [%4];"
                             : "=r"(v0), "=r"(v1), "=r"(v2), "=r"(v3) : "r"(addr));
                MMA16816(c[2*np],     qf[kk], v0, v1);
                MMA16816(c[2*np + 1], qf[kk], v2, v3);
            }
        }

        // ---- dequant corrections + online softmax ----
        float mx0 = -1e30f, mx1 = -1e30f;
        #pragma unroll
        for (int n8 = 0; n8 < 8; n8++) {
            int cc = n8 * 8 + 2 * tg;
            float4 Pa = sP4[cc], Pb = sP4[cc + 1];   // (al, be, ga, vs)
            c[n8][0] = (qa0 * Pa.x * c[n8][0] + qB0 * Pa.y + qc0 * Pa.z) * SCL;
            c[n8][1] = (qa0 * Pb.x * c[n8][1] + qB0 * Pb.y + qc0 * Pb.z) * SCL;
            c[n8][2] = (qa1 * Pa.x * c[n8][2] + qB1 * Pa.y + qc1 * Pa.z) * SCL;
            c[n8][3] = (qa1 * Pb.x * c[n8][3] + qB1 * Pb.y + qc1 * Pb.z) * SCL;
            mx0 = fmaxf(mx0, fmaxf(c[n8][0], c[n8][1]));
            mx1 = fmaxf(mx1, fmaxf(c[n8][2], c[n8][3]));
        }
        mx0 = fmaxf(mx0, __shfl_xor_sync(~0u, mx0, 1));
        mx0 = fmaxf(mx0, __shfl_xor_sync(~0u, mx0, 2));
        mx1 = fmaxf(mx1, __shfl_xor_sync(~0u, mx1, 1));
        mx1 = fmaxf(mx1, __shfl_xor_sync(~0u, mx1, 2));
        const float mn0 = fmaxf(m0, mx0), mn1 = fmaxf(m1, mx1);
        const bool nochange = (m0 == mn0) & (m1 == mn1);
        const float cr0 = ex2f(m0 - mn0), cr1 = ex2f(m1 - mn1);
        m0 = mn0; m1 = mn1;

        float pl0 = 0.f, pl1 = 0.f, pb0 = 0.f, pb1 = 0.f;
        #pragma unroll
        for (int n8 = 0; n8 < 8; n8++) {
            int cc = n8 * 8 + 2 * tg;
            float p00 = ex2f(c[n8][0] - mn0), p01 = ex2f(c[n8][1] - mn0);
            float p10 = ex2f(c[n8][2] - mn1), p11 = ex2f(c[n8][3] - mn1);
            pl0 += p00 + p01; pl1 += p10 + p11;
            float vs0 = sP4[cc].w,  vs1 = sP4[cc + 1].w;
            float vm0 = sVm[cc],    vm1 = sVm[cc + 1];
            pb0 += p00 * vm0 + p01 * vm1;
            pb1 += p10 * vm0 + p11 * vm1;
            __half2 t0 = __floats2half2_rn(p00 * vs0, p01 * vs1);
            __half2 t1 = __floats2half2_rn(p10 * vs0, p11 * vs1);
            c[n8][0] = __uint_as_float(*(unsigned*)&t0);   // pack P' in place (rows r0)
            c[n8][1] = __uint_as_float(*(unsigned*)&t1);   // rows r1
        }
        l0 = l0 * cr0 + pl0;  l1 = l1 * cr1 + pl1;
        bb0 = bb0 * cr0 + pb0; bb1 = bb1 * cr1 + pb1;
        if (!__all_sync(0xffffffffu, nochange)) {
            #pragma unroll
            for (int i = 0; i < 16; i++) {
                o[i][0] *= cr0; o[i][1] *= cr0; o[i][2] *= cr1; o[i][3] *= cr1;
            }
        }

        // ---- O += P' * Vcodes  (P' packed in c[n8][0..1]; V via ldmatrix.trans) ----
        #pragma unroll
        for (int kk = 0; kk < 4; kk++) {
            unsigned a[4] = { __float_as_uint(c[2*kk][0]),     __float_as_uint(c[2*kk][1]),
                              __float_as_uint(c[2*kk + 1][0]), __float_as_uint(c[2*kk + 1][1]) };
            #pragma unroll
            for (int nb = 0; nb < 8; nb++) {
                int rowl = kk * 16 + (lane & 15);
                int col  = nb * 16 + ((lane & 16) ? 8 : 0);
                unsigned addr = sVb + ((unsigned)(rowl * PITCH + col) << 1);
                unsigned v0, v1, v2, v3;
                asm volatile("ldmatrix.sync.aligned.m8n8.x4.trans.shared.b16 {%0,%1,%2,%3}, [%4];"
                             : "=r"(v0), "=r"(v1), "=r"(v2), "=r"(v3) : "r"(addr));
                MMA16816(o[2*nb],     a, v0, v1);
                MMA16816(o[2*nb + 1], a, v2, v3);
            }
        }
        __syncthreads();   // all reads of this stage done before it is re-filled at kb+1
    }

    // ---- epilogue: reduce l/bias across the quad, normalize, store fp32 ----
    l0  += __shfl_xor_sync(~0u, l0, 1);  l0  += __shfl_xor_sync(~0u, l0, 2);
    l1  += __shfl_xor_sync(~0u, l1, 1);  l1  += __shfl_xor_sync(~0u, l1, 2);
    bb0 += __shfl_xor_sync(~0u, bb0, 1); bb0 += __shfl_xor_sync(~0u, bb0, 2);
    bb1 += __shfl_xor_sync(~0u, bb1, 1); bb1 += __shfl_xor_sync(~0u, bb1, 2);
    const float iv0 = 1.f / l0, iv1 = 1.f / l1;
    float* O0 = out + (size_t)(q0 + r0) * NBH * HD + (size_t)bh * HD;
    float* O1 = out + (size_t)(q0 + r1) * NBH * HD + (size_t)bh * HD;
    #pragma unroll
    for (int i = 0; i < 16; i++) {
        int d0 = i * 8 + 2 * tg;
        float2 w0 = make_float2((o[i][0] + bb0) * iv0, (o[i][1] + bb0) * iv0);
        float2 w1 = make_float2((o[i][2] + bb1) * iv1, (o[i][3] + bb1) * iv1);
        *(float2*)(O0 + d0) = w0;
        *(float2*)(O1 + d0) = w1;
    }
}

extern "C" void kernel_launch(void* const* d_in, const int* in_sizes, int n_in,
                              void* d_out, int out_size) {
    const int*   q      = (const int*)d_in[0];
    const int*   k      = (const int*)d_in[1];
    const int*   v      = (const int*)d_in[2];
    const float* qmn    = (const float*)d_in[3];
    const float* qsc    = (const float*)d_in[4];
    const float* kmn    = (const float*)d_in[5];
    const float* ksc    = (const float*)d_in[6];
    const float* vmn    = (const float*)d_in[7];
    const float* vsc    = (const float*)d_in[8];

    (void)cudaFuncSetAttribute(attn_kernel, cudaFuncAttributeMaxDynamicSharedMemorySize, SMEM_BYTES);

    dim3 pg(SQ * NBH / 8, 3);
    prep_kernel<<<pg, 256>>>(q, k, v, kmn, ksc, vsc);

    dim3 ag(SQ / BM, NBH);   // qtile fastest -> concurrent CTAs share a head's K/V in L2
    attn_kernel<<<ag, NTHREADS, SMEM_BYTES>>>(qmn, qsc, vmn, (float*)d_out);
}

// round 11
// speedup vs baseline: 1.3408x; 1.2254x over previous
#include <cuda_runtime.h>
#include <cuda_fp16.h>
#include <cstdint>

#define SQ 2048
#define NBH 32
#define HD 128
#define BM 64            // q rows per CTA (4 warps x 16 rows)
#define BN 64
#define NTHREADS 128
#define PITCH 136        // half elements per V smem row (128 + 8 pad) = 272B
#define KTILE 2048       // bytes per K kk-step block (64 n * 32B); tile = 4*2048 = 8192
#define VTILE (BN*PITCH*2)   // 17408 bytes
// smem offsets
#define SM_K0 0
#define SM_V0 8192
#define SM_K1 25600
#define SM_V1 33792
#define SM_P0 51200
#define SM_P1 52480
#define SMEM_BYTES 53760
#define SCLF 0.12752836805103852f   // log2(e)/sqrt(128)

// Persistent scratch (no cudaMalloc allowed)
__device__ unsigned g_q8[SQ*NBH*32];   // permuted u8 codes, 128B/row as 32 u32
__device__ unsigned g_k8[SQ*NBH*32];
__device__ __half g_v[SQ*NBH*HD];
__device__ float4 g_qpar[SQ*NBH];      // (qa*SCL, (qa*qsum+128*qmin)*SCL, qmin*SCL, 0)
__device__ float4 g_kpar[SQ*NBH];      // (kscale, kmin, kscale*ksum, vscale)

// ---------------- prep: q/k int32 codes -> permuted u8 + params ----------------
// permuted byte order per 32-k chunk: [0-3][16-19][4-7][20-23][8-11][24-27][12-15][28-31]
__global__ void prep_qk8(const int* __restrict__ q, const int* __restrict__ k,
                         const float* __restrict__ qmin, const float* __restrict__ qscale,
                         const float* __restrict__ kmin, const float* __restrict__ kscale,
                         const float* __restrict__ vscale) {
    int warp = threadIdx.x >> 5, lane = threadIdx.x & 31;
    int row = blockIdx.x * 8 + warp;               // 0 .. S*BH-1
    int t = blockIdx.y;                            // 0=q, 1=k
    const int* src = (t == 0) ? q : k;
    unsigned* dst = (t == 0) ? g_q8 : g_k8;
    // output u32 index lane: orig k0 = (lane/8)*32 + ((lane&1)<<4) + (((lane&7)>>1)<<2)
    int k0 = ((lane >> 3) << 5) + ((lane & 1) << 4) + (((lane & 7) >> 1) << 2);
    int4 c = *(const int4*)(src + (size_t)row * HD + k0);
    unsigned packed = (unsigned)c.x | ((unsigned)c.y << 8) | ((unsigned)c.z << 16) | ((unsigned)c.w << 24);
    dst[(size_t)row * 32 + lane] = packed;
    int s = c.x + c.y + c.z + c.w;
    #pragma unroll
    for (int off = 16; off; off >>= 1) s += __shfl_xor_sync(0xffffffffu, s, off);
    if (lane == 0) {
        if (t == 0) {
            float qs = qscale[row], qm = qmin[row];
            g_qpar[row] = make_float4(qs * SCLF, (qs * (float)s + 128.f * qm) * SCLF, qm * SCLF, 0.f);
        } else {
            float ks = kscale[row];
            g_kpar[row] = make_float4(ks, kmin[row], ks * (float)s, vscale[row]);
        }
    }
}

// ---------------- prep: v int32 -> fp16 ----------------
__global__ void prep_v(const int* __restrict__ v) {
    int warp = threadIdx.x >> 5, lane = threadIdx.x & 31;
    int row = blockIdx.x * 8 + warp;
    int4 c = *((const int4*)(v + (size_t)row * HD) + lane);
    __half2 p0 = __floats2half2_rn((float)c.x, (float)c.y);
    __half2 p1 = __floats2half2_rn((float)c.z, (float)c.w);
    uint2 w; w.x = *(unsigned*)&p0; w.y = *(unsigned*)&p1;
    *((uint2*)(g_v + (size_t)row * HD) + lane) = w;
}

__device__ __forceinline__ float ex2f(float x) {
    float y; asm("ex2.approx.f32 %0, %1;" : "=f"(y) : "f"(x)); return y;
}
__device__ __forceinline__ void cp16(uint32_t dst, const void* src) {
    asm volatile("cp.async.cg.shared.global [%0], [%1], 16;" :: "r"(dst), "l"(src));
}
__device__ __forceinline__ void cp4(uint32_t dst, const void* src) {
    asm volatile("cp.async.ca.shared.global [%0], [%1], 4;" :: "r"(dst), "l"(src));
}
__device__ __forceinline__ uint2 lds64(uint32_t a) {
    uint2 r; asm volatile("ld.shared.v2.u32 {%0,%1}, [%2];" : "=r"(r.x), "=r"(r.y) : "r"(a));
    return r;
}
__device__ __forceinline__ uint32_t smem_u32(const void* p) {
    uint32_t a;
    asm("{ .reg .u64 t; cvta.to.shared.u64 t, %1; cvt.u32.u64 %0, t; }" : "=r"(a) : "l"(p));
    return a;
}

#define MMAU8(cc, aa, b0v, b1v) \
    asm volatile("mma.sync.aligned.m16n8k32.row.col.s32.u8.u8.s32 " \
        "{%0,%1,%2,%3},{%4,%5,%6,%7},{%8,%9},{%0,%1,%2,%3};" \
        : "+r"(cc[0]), "+r"(cc[1]), "+r"(cc[2]), "+r"(cc[3]) \
        : "r"(aa[0]), "r"(aa[1]), "r"(aa[2]), "r"(aa[3]), "r"(b0v), "r"(b1v))

#define MMA16816(cc, aa, b0v, b1v) \
    asm volatile("mma.sync.aligned.m16n8k16.row.col.f32.f16.f16.f32 " \
        "{%0,%1,%2,%3},{%4,%5,%6,%7},{%8,%9},{%0,%1,%2,%3};" \
        : "+f"(cc[0]), "+f"(cc[1]), "+f"(cc[2]), "+f"(cc[3]) \
        : "r"(aa[0]), "r"(aa[1]), "r"(aa[2]), "r"(aa[3]), "r"(b0v), "r"(b1v))

// ---------------- main: flash attention, u8 QK + fp16 PV, 2-stage cp.async ----------------
__global__ __launch_bounds__(NTHREADS, 3) void attn_kernel(
    const float* __restrict__ vmin, float* __restrict__ out)
{
    extern __shared__ __align__(16) unsigned char smem_raw[];
    const uint32_t sb = smem_u32(smem_raw);

    const int tid = threadIdx.x, warp = tid >> 5, lane = tid & 31;
    const int g = lane >> 2, tg = lane & 3;
    const int bh = blockIdx.y, q0 = blockIdx.x * BM;

    // ---- prologue: Q tile (permuted u8) into smem (overlays stage-0 K/V), then A frags ----
    {
        const char* Qg = (const char*)g_q8 + ((size_t)q0 * NBH + bh) * 128;
        #pragma unroll
        for (int j = 0; j < 4; j++) {
            int c = tid + j * NTHREADS;            // 0..511 ; Q smem: kk*2048 + row*32 + w
            int kk = c >> 7, rem = c & 127;
            int row = rem >> 1, w = (c & 1) << 4;
            cp16(sb + (uint32_t)(kk * 2048 + row * 32 + w),
                 Qg + (size_t)row * NBH * 128 + kk * 32 + w);
        }
        asm volatile("cp.async.commit_group;" ::: "memory");
        asm volatile("cp.async.wait_group 0;" ::: "memory");
        __syncthreads();
    }
    unsigned qf[4][4];
    const int r0 = warp * 16 + g, r1 = r0 + 8;
    #pragma unroll
    for (int kk = 0; kk < 4; kk++) {
        uint2 lo = lds64(sb + (uint32_t)(kk * 2048 + r0 * 32 + tg * 8));
        uint2 hi = lds64(sb + (uint32_t)(kk * 2048 + r1 * 32 + tg * 8));
        qf[kk][0] = lo.x; qf[kk][1] = hi.x; qf[kk][2] = lo.y; qf[kk][3] = hi.y;
    }
    const size_t qi0 = (size_t)(q0 + r0) * NBH + bh, qi1 = qi0 + 8 * NBH;
    const float4 qp0 = g_qpar[qi0], qp1 = g_qpar[qi1];
    const float qa0 = qp0.x, qB0 = qp0.y, qc0 = qp0.z;
    const float qa1 = qp1.x, qB1 = qp1.y, qc1 = qp1.z;
    __syncthreads();   // done reading Q smem; stage-0 buffers may be overwritten

    // ---- cp.async tile issue ----
    auto issue_tile = [&](int kb, int st) {
        const int kbase = kb * BN;
        const uint32_t koff = st ? SM_K1 : SM_K0;
        const uint32_t voff = st ? SM_V1 : SM_V0;
        const uint32_t poff = st ? SM_P1 : SM_P0;
        const char* Kg = (const char*)g_k8 + ((size_t)kbase * NBH + bh) * 128;
        const __half* Vg = g_v + ((size_t)kbase * NBH + bh) * HD;
        #pragma unroll
        for (int j = 0; j < 4; j++) {
            int c = tid + j * NTHREADS;            // 0..511 ; K smem: kk*2048 + n*32 + w
            int kk = c >> 7, rem = c & 127;
            int n = rem >> 1, w = (c & 1) << 4;
            cp16(sb + koff + (uint32_t)(kk * 2048 + n * 32 + w),
                 Kg + (size_t)n * NBH * 128 + kk * 32 + w);
        }
        #pragma unroll
        for (int j = 0; j < 8; j++) {
            int chunk = tid + j * NTHREADS;        // 0..1023
            int row = chunk >> 4, c16 = chunk & 15;
            cp16(sb + voff + (uint32_t)(row * PITCH + c16 * 8) * 2,
                 Vg + (size_t)row * NBH * HD + c16 * 8);
        }
        if (tid < 64) cp16(sb + poff + tid * 16, g_kpar + (size_t)(kbase + tid) * NBH + bh);
        else cp4(sb + poff + 1024 + (tid - 64) * 4, vmin + (size_t)(kbase + tid - 64) * NBH + bh);
        asm volatile("cp.async.commit_group;" ::: "memory");
    };

    issue_tile(0, 0);

    float o[16][4];
    #pragma unroll
    for (int i = 0; i < 16; i++) { o[i][0] = o[i][1] = o[i][2] = o[i][3] = 0.f; }
    float m0 = -1e30f, m1 = -1e30f, l0 = 0.f, l1 = 0.f, bb0 = 0.f, bb1 = 0.f;

    for (int kb = 0; kb < SQ / BN; kb++) {
        const int st = kb & 1;
        if (kb + 1 < SQ / BN) {
            issue_tile(kb + 1, st ^ 1);
            asm volatile("cp.async.wait_group 1;" ::: "memory");
        } else {
            asm volatile("cp.async.wait_group 0;" ::: "memory");
        }
        __syncthreads();   // tile kb visible

        const uint32_t koff = st ? SM_K1 : SM_K0;
        const uint32_t voff = st ? SM_V1 : SM_V0;
        const uint32_t poff = st ? SM_P1 : SM_P0;
        const float4* sP4 = (const float4*)(smem_raw + poff);
        const float* sVm = (const float*)(smem_raw + poff + 1024);
        const uint32_t sVb = sb + voff;

        // ---- S = Q * K^T in u8 MMA (exact s32) ----
        int ci[8][4];
        #pragma unroll
        for (int i = 0; i < 8; i++) { ci[i][0] = ci[i][1] = ci[i][2] = ci[i][3] = 0; }
        const uint32_t lbase = sb + koff + (uint32_t)(g * 32 + tg * 8);
        #pragma unroll
        for (int kk = 0; kk < 4; kk++) {
            #pragma unroll
            for (int n8 = 0; n8 < 8; n8++) {
                uint2 b = lds64(lbase + (uint32_t)(kk * 2048 + n8 * 256));
                MMAU8(ci[n8], qf[kk], b.x, b.y);
            }
        }

        // ---- dequant corrections + online softmax ----
        float cf[8][4];
        float mx0 = -1e30f, mx1 = -1e30f;
        #pragma unroll
        for (int n8 = 0; n8 < 8; n8++) {
            int cc = n8 * 8 + 2 * tg;
            float4 Pa = sP4[cc], Pb = sP4[cc + 1];   // (ks, km, ks*ksum, vs)
            cf[n8][0] = fmaf(qa0 * Pa.x, (float)ci[n8][0], fmaf(qB0, Pa.y, qc0 * Pa.z));
            cf[n8][1] = fmaf(qa0 * Pb.x, (float)ci[n8][1], fmaf(qB0, Pb.y, qc0 * Pb.z));
            cf[n8][2] = fmaf(qa1 * Pa.x, (float)ci[n8][2], fmaf(qB1, Pa.y, qc1 * Pa.z));
            cf[n8][3] = fmaf(qa1 * Pb.x, (float)ci[n8][3], fmaf(qB1, Pb.y, qc1 * Pb.z));
            mx0 = fmaxf(mx0, fmaxf(cf[n8][0], cf[n8][1]));
            mx1 = fmaxf(mx1, fmaxf(cf[n8][2], cf[n8][3]));
        }
        mx0 = fmaxf(mx0, __shfl_xor_sync(~0u, mx0, 1));
        mx0 = fmaxf(mx0, __shfl_xor_sync(~0u, mx0, 2));
        mx1 = fmaxf(mx1, __shfl_xor_sync(~0u, mx1, 1));
        mx1 = fmaxf(mx1, __shfl_xor_sync(~0u, mx1, 2));
        const float mn0 = fmaxf(m0, mx0), mn1 = fmaxf(m1, mx1);
        const bool nochange = (m0 == mn0) & (m1 == mn1);
        const float cr0 = ex2f(m0 - mn0), cr1 = ex2f(m1 - mn1);
        m0 = mn0; m1 = mn1;

        float pl0 = 0.f, pl1 = 0.f, pb0 = 0.f, pb1 = 0.f;
        #pragma unroll
        for (int n8 = 0; n8 < 8; n8++) {
            int cc = n8 * 8 + 2 * tg;
            float p00 = ex2f(cf[n8][0] - mn0), p01 = ex2f(cf[n8][1] - mn0);
            float p10 = ex2f(cf[n8][2] - mn1), p11 = ex2f(cf[n8][3] - mn1);
            pl0 += p00 + p01; pl1 += p10 + p11;
            float vs0 = sP4[cc].w,  vs1 = sP4[cc + 1].w;
            float vm0 = sVm[cc],    vm1 = sVm[cc + 1];
            pb0 = fmaf(p00, vm0, fmaf(p01, vm1, pb0));
            pb1 = fmaf(p10, vm0, fmaf(p11, vm1, pb1));
            __half2 t0 = __floats2half2_rn(p00 * vs0, p01 * vs1);
            __half2 t1 = __floats2half2_rn(p10 * vs0, p11 * vs1);
            ci[n8][0] = (int)*(unsigned*)&t0;   // pack P' in place (rows r0)
            ci[n8][1] = (int)*(unsigned*)&t1;   // rows r1
        }
        l0 = l0 * cr0 + pl0;  l1 = l1 * cr1 + pl1;
        bb0 = bb0 * cr0 + pb0; bb1 = bb1 * cr1 + pb1;
        if (!__all_sync(0xffffffffu, nochange)) {
            #pragma unroll
            for (int i = 0; i < 16; i++) {
                o[i][0] *= cr0; o[i][1] *= cr0; o[i][2] *= cr1; o[i][3] *= cr1;
            }
        }

        // ---- O += P' * Vcodes  (fp16 MMA; V via ldmatrix.trans) ----
        #pragma unroll
        for (int kk = 0; kk < 4; kk++) {
            unsigned a[4] = { (unsigned)ci[2*kk][0], (unsigned)ci[2*kk][1],
                              (unsigned)ci[2*kk + 1][0], (unsigned)ci[2*kk + 1][1] };
            #pragma unroll
            for (int nb = 0; nb < 8; nb++) {
                int rowl = kk * 16 + (lane & 15);
                int col  = nb * 16 + ((lane & 16) ? 8 : 0);
                unsigned addr = sVb + ((unsigned)(rowl * PITCH + col) << 1);
                unsigned v0, v1, v2, v3;
                asm volatile("ldmatrix.sync.aligned.m8n8.x4.trans.shared.b16 {%0,%1,%2,%3}, [%4];"
                             : "=r"(v0), "=r"(v1), "=r"(v2), "=r"(v3) : "r"(addr));
                MMA16816(o[2*nb],     a, v0, v1);
                MMA16816(o[2*nb + 1], a, v2, v3);
            }
        }
        __syncthreads();   // all reads of this stage done before refill
    }

    // ---- epilogue: reduce l/bias across the quad, normalize, store fp32 ----
    l0  += __shfl_xor_sync(~0u, l0, 1);  l0  += __shfl_xor_sync(~0u, l0, 2);
    l1  += __shfl_xor_sync(~0u, l1, 1);  l1  += __shfl_xor_sync(~0u, l1, 2);
    bb0 += __shfl_xor_sync(~0u, bb0, 1); bb0 += __shfl_xor_sync(~0u, bb0, 2);
    bb1 += __shfl_xor_sync(~0u, bb1, 1); bb1 += __shfl_xor_sync(~0u, bb1, 2);
    const float iv0 = 1.f / l0, iv1 = 1.f / l1;
    float* O0 = out + (size_t)(q0 + r0) * NBH * HD + (size_t)bh * HD;
    float* O1 = out + (size_t)(q0 + r1) * NBH * HD + (size_t)bh * HD;
    #pragma unroll
    for (int i = 0; i < 16; i++) {
        int d0 = i * 8 + 2 * tg;
        float2 w0 = make_float2((o[i][0] + bb0) * iv0, (o[i][1] + bb0) * iv0);
        float2 w1 = make_float2((o[i][2] + bb1) * iv1, (o[i][3] + bb1) * iv1);
        *(float2*)(O0 + d0) = w0;
        *(float2*)(O1 + d0) = w1;
    }
}

extern "C" void kernel_launch(void* const* d_in, const int* in_sizes, int n_in,
                              void* d_out, int out_size) {
    const int*   q   = (const int*)d_in[0];
    const int*   k   = (const int*)d_in[1];
    const int*   v   = (const int*)d_in[2];
    const float* qmn = (const float*)d_in[3];
    const float* qsc = (const float*)d_in[4];
    const float* kmn = (const float*)d_in[5];
    const float* ksc = (const float*)d_in[6];
    const float* vmn = (const float*)d_in[7];
    const float* vsc = (const float*)d_in[8];

    (void)cudaFuncSetAttribute(attn_kernel, cudaFuncAttributeMaxDynamicSharedMemorySize, SMEM_BYTES);

    dim3 pg(SQ * NBH / 8, 2);
    prep_qk8<<<pg, 256>>>(q, k, qmn, qsc, kmn, ksc, vsc);
    prep_v<<<SQ * NBH / 8, 256>>>(v);

    dim3 ag(SQ / BM, NBH);   // qtile fastest -> concurrent CTAs share a head's K/V in L2
    attn_kernel<<<ag, NTHREADS, SMEM_BYTES>>>(vmn, (float*)d_out);
}

// round 13
// speedup vs baseline: 1.5361x; 1.1457x over previous
#include <cuda_runtime.h>
#include <cuda_fp16.h>
#include <cstdint>

#define SQ 2048
#define NBH 32
#define HD 128
#define BM 64            // q rows per CTA (4 warps x 16 rows)
#define BN 64
#define NTHREADS 128
#define PITCH 136        // half elements per V smem row: 128 data + [1, vm, 0..] = 272B
#define KTILE 2048       // bytes per K kk-step block (64 n * 32B); tile = 4*2048 = 8192
// smem offsets
#define SM_K0 0
#define SM_V0 8192
#define SM_K1 25600
#define SM_V1 33792
#define SM_P0 51200
#define SM_P1 52480
#define SMEM_BYTES 53760
#define SCLF 0.12752836805103852f   // log2(e)/sqrt(128)

// Persistent scratch (no cudaMalloc allowed)
__device__ unsigned g_q8[SQ*NBH*32];   // permuted u8 codes, 128B/row as 32 u32
__device__ unsigned g_k8[SQ*NBH*32];
__device__ __half g_va[(size_t)SQ*NBH*PITCH]; // augmented dequant V: [vs*code x128, 1, vm, 0 x6]
__device__ float4 g_qpar[SQ*NBH];      // (qa*SCL, (qa*qsum+128*qmin)*SCL, qmin*SCL, 0)
__device__ float4 g_kpar[SQ*NBH];      // (kscale, kmin, kscale*ksum, -)

// ---------------- prep: q/k int32 codes -> permuted u8 + params ----------------
// permuted byte order per 32-k chunk: [0-3][16-19][4-7][20-23][8-11][24-27][12-15][28-31]
__global__ void prep_qk8(const int* __restrict__ q, const int* __restrict__ k,
                         const float* __restrict__ qmin, const float* __restrict__ qscale,
                         const float* __restrict__ kmin, const float* __restrict__ kscale) {
    int warp = threadIdx.x >> 5, lane = threadIdx.x & 31;
    int row = blockIdx.x * 8 + warp;               // 0 .. S*BH-1
    int t = blockIdx.y;                            // 0=q, 1=k
    const int* src = (t == 0) ? q : k;
    unsigned* dst = (t == 0) ? g_q8 : g_k8;
    int k0 = ((lane >> 3) << 5) + ((lane & 1) << 4) + (((lane & 7) >> 1) << 2);
    int4 c = *(const int4*)(src + (size_t)row * HD + k0);
    unsigned packed = (unsigned)c.x | ((unsigned)c.y << 8) | ((unsigned)c.z << 16) | ((unsigned)c.w << 24);
    dst[(size_t)row * 32 + lane] = packed;
    int s = c.x + c.y + c.z + c.w;
    #pragma unroll
    for (int off = 16; off; off >>= 1) s += __shfl_xor_sync(0xffffffffu, s, off);
    if (lane == 0) {
        if (t == 0) {
            float qs = qscale[row], qm = qmin[row];
            g_qpar[row] = make_float4(qs * SCLF, (qs * (float)s + 128.f * qm) * SCLF, qm * SCLF, 0.f);
        } else {
            float ks = kscale[row];
            g_kpar[row] = make_float4(ks, kmin[row], ks * (float)s, 0.f);
        }
    }
}

// ---------------- prep: v int32 -> augmented dequant fp16 rows ----------------
__global__ void prep_va(const int* __restrict__ v,
                        const float* __restrict__ vmin, const float* __restrict__ vscale) {
    int warp = threadIdx.x >> 5, lane = threadIdx.x & 31;
    int row = blockIdx.x * 8 + warp;
    float vs = vscale[row];
    int4 c = *((const int4*)(v + (size_t)row * HD) + lane);
    __half2 p0 = __floats2half2_rn(vs * (float)c.x, vs * (float)c.y);
    __half2 p1 = __floats2half2_rn(vs * (float)c.z, vs * (float)c.w);
    uint2 w; w.x = *(unsigned*)&p0; w.y = *(unsigned*)&p1;
    *((uint2*)(g_va + (size_t)row * PITCH) + lane) = w;
    if (lane == 0) {
        __half ext[8];
        ext[0] = __float2half_rn(1.0f);
        ext[1] = __float2half_rn(vmin[row]);
        #pragma unroll
        for (int i = 2; i < 8; i++) ext[i] = __float2half_rn(0.f);
        *(uint4*)(g_va + (size_t)row * PITCH + 128) = *(uint4*)ext;
    }
}

__device__ __forceinline__ void cp16(uint32_t dst, const void* src) {
    asm volatile("cp.async.cg.shared.global [%0], [%1], 16;" :: "r"(dst), "l"(src));
}
__device__ __forceinline__ uint2 lds64(uint32_t a) {
    uint2 r; asm volatile("ld.shared.v2.u32 {%0,%1}, [%2];" : "=r"(r.x), "=r"(r.y) : "r"(a));
    return r;
}
__device__ __forceinline__ uint32_t smem_u32(const void* p) {
    uint32_t a;
    asm("{ .reg .u64 t; cvta.to.shared.u64 t, %1; cvt.u32.u64 %0, t; }" : "=r"(a) : "l"(p));
    return a;
}

#define MMAU8(cc, aa, b0v, b1v) \
    asm volatile("mma.sync.aligned.m16n8k32.row.col.s32.u8.u8.s32 " \
        "{%0,%1,%2,%3},{%4,%5,%6,%7},{%8,%9},{%0,%1,%2,%3};" \
        : "+r"(cc[0]), "+r"(cc[1]), "+r"(cc[2]), "+r"(cc[3]) \
        : "r"(aa[0]), "r"(aa[1]), "r"(aa[2]), "r"(aa[3]), "r"(b0v), "r"(b1v))

#define MMA16816(cc, aa, b0v, b1v) \
    asm volatile("mma.sync.aligned.m16n8k16.row.col.f32.f16.f16.f32 " \
        "{%0,%1,%2,%3},{%4,%5,%6,%7},{%8,%9},{%0,%1,%2,%3};" \
        : "+f"(cc[0]), "+f"(cc[1]), "+f"(cc[2]), "+f"(cc[3]) \
        : "r"(aa[0]), "r"(aa[1]), "r"(aa[2]), "r"(aa[3]), "r"(b0v), "r"(b1v))

// ---------------- main: flash attention, u8 QK + fp16 PV with l/b in MMA ----------------
__global__ __launch_bounds__(NTHREADS, 3) void attn_kernel(float* __restrict__ out)
{
    extern __shared__ __align__(16) unsigned char smem_raw[];
    const uint32_t sb = smem_u32(smem_raw);

    const int tid = threadIdx.x, warp = tid >> 5, lane = tid & 31;
    const int g = lane >> 2, tg = lane & 3;
    const int bh = blockIdx.y, q0 = blockIdx.x * BM;

    // ---- prologue: Q tile (permuted u8) into smem (overlays stage-0 K/V), then A frags ----
    {
        const char* Qg = (const char*)g_q8 + ((size_t)q0 * NBH + bh) * 128;
        #pragma unroll
        for (int j = 0; j < 4; j++) {
            int c = tid + j * NTHREADS;            // 0..511 ; Q smem: kk*2048 + row*32 + w
            int kk = c >> 7, rem = c & 127;
            int row = rem >> 1, w = (c & 1) << 4;
            cp16(sb + (uint32_t)(kk * 2048 + row * 32 + w),
                 Qg + (size_t)row * NBH * 128 + kk * 32 + w);
        }
        asm volatile("cp.async.commit_group;" ::: "memory");
        asm volatile("cp.async.wait_group 0;" ::: "memory");
        __syncthreads();
    }
    unsigned qf[4][4];
    const int r0 = warp * 16 + g, r1 = r0 + 8;
    #pragma unroll
    for (int kk = 0; kk < 4; kk++) {
        uint2 lo = lds64(sb + (uint32_t)(kk * 2048 + r0 * 32 + tg * 8));
        uint2 hi = lds64(sb + (uint32_t)(kk * 2048 + r1 * 32 + tg * 8));
        qf[kk][0] = lo.x; qf[kk][1] = hi.x; qf[kk][2] = lo.y; qf[kk][3] = hi.y;
    }
    const size_t qi0 = (size_t)(q0 + r0) * NBH + bh, qi1 = qi0 + 8 * NBH;
    const float4 qp0 = g_qpar[qi0], qp1 = g_qpar[qi1];
    const float qa0 = qp0.x, qB0 = qp0.y, qc0 = qp0.z;
    const float qa1 = qp1.x, qB1 = qp1.y, qc1 = qp1.z;
    __syncthreads();   // done reading Q smem; stage-0 buffers may be overwritten

    // ---- cp.async tile issue ----
    auto issue_tile = [&](int kb, int st) {
        const int kbase = kb * BN;
        const uint32_t koff = st ? SM_K1 : SM_K0;
        const uint32_t voff = st ? SM_V1 : SM_V0;
        const uint32_t poff = st ? SM_P1 : SM_P0;
        const char* Kg = (const char*)g_k8 + ((size_t)kbase * NBH + bh) * 128;
        const __half* Vg = g_va + ((size_t)kbase * NBH + bh) * PITCH;
        #pragma unroll
        for (int j = 0; j < 4; j++) {
            int c = tid + j * NTHREADS;            // 0..511 ; K smem: kk*2048 + n*32 + w
            int kk = c >> 7, rem = c & 127;
            int n = rem >> 1, w = (c & 1) << 4;
            cp16(sb + koff + (uint32_t)(kk * 2048 + n * 32 + w),
                 Kg + (size_t)n * NBH * 128 + kk * 32 + w);
        }
        #pragma unroll
        for (int j = 0; j < 8; j++) {
            int chunk = tid + j * NTHREADS;        // 0..1023 : cols 0..127 (256B/row)
            int row = chunk >> 4, c16 = chunk & 15;
            cp16(sb + voff + (uint32_t)(row * PITCH + c16 * 8) * 2,
                 Vg + (size_t)row * NBH * PITCH + c16 * 8);
        }
        if (tid < 64) {
            // augmented cols 128..135 (16B tail of each row)
            cp16(sb + voff + (uint32_t)(tid * PITCH + 128) * 2,
                 Vg + (size_t)tid * NBH * PITCH + 128);
        } else {
            int key = tid - 64;
            cp16(sb + poff + key * 16, g_kpar + (size_t)(kbase + key) * NBH + bh);
        }
        asm volatile("cp.async.commit_group;" ::: "memory");
    };

    issue_tile(0, 0);

    float o[16][4], ox[4];
    #pragma unroll
    for (int i = 0; i < 16; i++) { o[i][0] = o[i][1] = o[i][2] = o[i][3] = 0.f; }
    ox[0] = ox[1] = ox[2] = ox[3] = 0.f;
    float m0 = -1e30f, m1 = -1e30f;

    for (int kb = 0; kb < SQ / BN; kb++) {
        const int st = kb & 1;
        if (kb + 1 < SQ / BN) {
            issue_tile(kb + 1, st ^ 1);
            asm volatile("cp.async.wait_group 1;" ::: "memory");
        } else {
            asm volatile("cp.async.wait_group 0;" ::: "memory");
        }
        __syncthreads();   // tile kb visible

        const uint32_t koff = st ? SM_K1 : SM_K0;
        const uint32_t voff = st ? SM_V1 : SM_V0;
        const uint32_t poff = st ? SM_P1 : SM_P0;
        const float4* sP4 = (const float4*)(smem_raw + poff);
        const uint32_t sVb = sb + voff;

        // ---- S = Q * K^T in u8 MMA (exact s32) ----
        int ci[8][4];
        #pragma unroll
        for (int i = 0; i < 8; i++) { ci[i][0] = ci[i][1] = ci[i][2] = ci[i][3] = 0; }
        const uint32_t lbase = sb + koff + (uint32_t)(g * 32 + tg * 8);
        #pragma unroll
        for (int kk = 0; kk < 4; kk++) {
            #pragma unroll
            for (int n8 = 0; n8 < 8; n8++) {
                uint2 b = lds64(lbase + (uint32_t)(kk * 2048 + n8 * 256));
                MMAU8(ci[n8], qf[kk], b.x, b.y);
            }
        }

        // ---- dequant corrections + online softmax ----
        float cf[8][4];
        float mx0 = -1e30f, mx1 = -1e30f;
        #pragma unroll
        for (int n8 = 0; n8 < 8; n8++) {
            int cc = n8 * 8 + 2 * tg;
            float4 Pa = sP4[cc], Pb = sP4[cc + 1];   // (ks, km, ks*ksum, -)
            cf[n8][0] = fmaf(qa0 * Pa.x, (float)ci[n8][0], fmaf(qB0, Pa.y, qc0 * Pa.z));
            cf[n8][1] = fmaf(qa0 * Pb.x, (float)ci[n8][1], fmaf(qB0, Pb.y, qc0 * Pb.z));
            cf[n8][2] = fmaf(qa1 * Pa.x, (float)ci[n8][2], fmaf(qB1, Pa.y, qc1 * Pa.z));
            cf[n8][3] = fmaf(qa1 * Pb.x, (float)ci[n8][3], fmaf(qB1, Pb.y, qc1 * Pb.z));
            mx0 = fmaxf(mx0, fmaxf(cf[n8][0], cf[n8][1]));
            mx1 = fmaxf(mx1, fmaxf(cf[n8][2], cf[n8][3]));
        }
        mx0 = fmaxf(mx0, __shfl_xor_sync(~0u, mx0, 1));
        mx0 = fmaxf(mx0, __shfl_xor_sync(~0u, mx0, 2));
        mx1 = fmaxf(mx1, __shfl_xor_sync(~0u, mx1, 1));
        mx1 = fmaxf(mx1, __shfl_xor_sync(~0u, mx1, 2));
        const float mn0 = fmaxf(m0, mx0), mn1 = fmaxf(m1, mx1);
        const bool nochange = (m0 == mn0) & (m1 == mn1);
        float cr0, cr1;
        asm("ex2.approx.f32 %0, %1;" : "=f"(cr0) : "f"(m0 - mn0));
        asm("ex2.approx.f32 %0, %1;" : "=f"(cr1) : "f"(m1 - mn1));
        m0 = mn0; m1 = mn1;

        // ---- p = 2^(S - m) in fp16 pairs (MUFU f16x2); becomes PV A operand directly ----
        #pragma unroll
        for (int n8 = 0; n8 < 8; n8++) {
            __half2 x0 = __floats2half2_rn(cf[n8][0] - mn0, cf[n8][1] - mn0);
            __half2 x1 = __floats2half2_rn(cf[n8][2] - mn1, cf[n8][3] - mn1);
            __half2 p0 = h2exp2(x0);
            __half2 p1 = h2exp2(x1);
            ci[n8][0] = (int)*(unsigned*)&p0;   // rows r0, keys cc..cc+1
            ci[n8][1] = (int)*(unsigned*)&p1;   // rows r1
        }
        if (!__all_sync(0xffffffffu, nochange)) {
            #pragma unroll
            for (int i = 0; i < 16; i++) {
                o[i][0] *= cr0; o[i][1] *= cr0; o[i][2] *= cr1; o[i][3] *= cr1;
            }
            ox[0] *= cr0; ox[1] *= cr0; ox[2] *= cr1; ox[3] *= cr1;
        }

        // ---- O += p * Vaug  (fp16 MMA; V via ldmatrix.trans; cols 128/129 = l/b) ----
        #pragma unroll
        for (int kk = 0; kk < 4; kk++) {
            unsigned a[4] = { (unsigned)ci[2*kk][0], (unsigned)ci[2*kk][1],
                              (unsigned)ci[2*kk + 1][0], (unsigned)ci[2*kk + 1][1] };
            #pragma unroll
            for (int nb = 0; nb < 8; nb++) {
                int rowl = kk * 16 + (lane & 15);
                int col  = nb * 16 + ((lane & 16) ? 8 : 0);
                unsigned addr = sVb + ((unsigned)(rowl * PITCH + col) << 1);
                unsigned v0, v1, v2, v3;
                asm volatile("ldmatrix.sync.aligned.m8n8.x4.trans.shared.b16 {%0,%1,%2,%3}, [%4];"
                             : "=r"(v0), "=r"(v1), "=r"(v2), "=r"(v3) : "r"(addr));
                MMA16816(o[2*nb],     a, v0, v1);
                MMA16816(o[2*nb + 1], a, v2, v3);
            }
            {   // extra n8 block: cols 128..135 (l, b, zeros)
                int rowl = kk * 16 + (lane & 15);
                unsigned addr = sVb + ((unsigned)(rowl * PITCH + 128) << 1);
                unsigned v0, v1;
                asm volatile("ldmatrix.sync.aligned.m8n8.x2.trans.shared.b16 {%0,%1}, [%2];"
                             : "=r"(v0), "=r"(v1) : "r"(addr));
                MMA16816(ox, a, v0, v1);
            }
        }
        __syncthreads();   // all reads of this stage done before refill
    }

    // ---- epilogue: l/b from MMA cols 128/129 (tg==0 lane), normalize, store fp32 ----
    const int qlead = lane & 28;
    const float l0 = __shfl_sync(0xffffffffu, ox[0], qlead);
    const float b0 = __shfl_sync(0xffffffffu, ox[1], qlead);
    const float l1 = __shfl_sync(0xffffffffu, ox[2], qlead);
    const float b1 = __shfl_sync(0xffffffffu, ox[3], qlead);
    const float iv0 = 1.f / l0, iv1 = 1.f / l1;
    float* O0 = out + (size_t)(q0 + r0) * NBH * HD + (size_t)bh * HD;
    float* O1 = out + (size_t)(q0 + r1) * NBH * HD + (size_t)bh * HD;
    #pragma unroll
    for (int i = 0; i < 16; i++) {
        int d0 = i * 8 + 2 * tg;
        float2 w0 = make_float2((o[i][0] + b0) * iv0, (o[i][1] + b0) * iv0);
        float2 w1 = make_float2((o[i][2] + b1) * iv1, (o[i][3] + b1) * iv1);
        *(float2*)(O0 + d0) = w0;
        *(float2*)(O1 + d0) = w1;
    }
}

extern "C" void kernel_launch(void* const* d_in, const int* in_sizes, int n_in,
                              void* d_out, int out_size) {
    const int*   q   = (const int*)d_in[0];
    const int*   k   = (const int*)d_in[1];
    const int*   v   = (const int*)d_in[2];
    const float* qmn = (const float*)d_in[3];
    const float* qsc = (const float*)d_in[4];
    const float* kmn = (const float*)d_in[5];
    const float* ksc = (const float*)d_in[6];
    const float* vmn = (const float*)d_in[7];
    const float* vsc = (const float*)d_in[8];

    (void)cudaFuncSetAttribute(attn_kernel, cudaFuncAttributeMaxDynamicSharedMemorySize, SMEM_BYTES);

    dim3 pg(SQ * NBH / 8, 2);
    prep_qk8<<<pg, 256>>>(q, k, qmn, qsc, kmn, ksc);
    prep_va<<<SQ * NBH / 8, 256>>>(v, vmn, vsc);

    dim3 ag(SQ / BM, NBH);   // qtile fastest -> concurrent CTAs share a head's K/V in L2
    attn_kernel<<<ag, NTHREADS, SMEM_BYTES>>>((float*)d_out);
}

// round 14
// speedup vs baseline: 1.5671x; 1.0202x over previous
#include <cuda_runtime.h>
#include <cuda_fp16.h>
#include <cstdint>

#define SQ 2048
#define NBH 32
#define HD 128
#define BM 64            // q rows per CTA (4 warps x 16 rows)
#define BN 64
#define NTHREADS 128
#define PITCH 136        // half elements per V smem row: 128 data + [1, vm, 0..] = 272B
// smem offsets
#define SM_K0 0
#define SM_V0 8192
#define SM_K1 25600
#define SM_V1 33792
#define SM_P0 51200
#define SM_P1 52480
#define SMEM_BYTES 53760
#define SCLF 0.12752836805103852f   // log2(e)/sqrt(128)

// Persistent scratch (no cudaMalloc allowed)
__device__ unsigned g_k8[SQ*NBH*32];   // permuted u8 codes, 128B/row as 32 u32
__device__ __half g_va[(size_t)SQ*NBH*PITCH]; // augmented dequant V: [vs*code x128, 1, vm, 0 x6]
__device__ float4 g_kpar[SQ*NBH];      // (kscale, kmin, kscale*ksum, -)

// ---------------- prep: K codes -> permuted u8 + params ; V -> augmented dequant fp16 ----------------
// permuted byte order per 32-k chunk: [0-3][16-19][4-7][20-23][8-11][24-27][12-15][28-31]
__global__ void prep_kv(const int* __restrict__ k, const int* __restrict__ v,
                        const float* __restrict__ kmin, const float* __restrict__ kscale,
                        const float* __restrict__ vmin, const float* __restrict__ vscale) {
    int warp = threadIdx.x >> 5, lane = threadIdx.x & 31;
    int row = blockIdx.x * 8 + warp;               // 0 .. S*BH-1
    if (blockIdx.y == 0) {
        // ---- K path ----
        int k0 = ((lane >> 3) << 5) + ((lane & 1) << 4) + (((lane & 7) >> 1) << 2);
        int4 c = *(const int4*)(k + (size_t)row * HD + k0);
        unsigned packed = (unsigned)c.x | ((unsigned)c.y << 8) | ((unsigned)c.z << 16) | ((unsigned)c.w << 24);
        g_k8[(size_t)row * 32 + lane] = packed;
        int s = c.x + c.y + c.z + c.w;
        #pragma unroll
        for (int off = 16; off; off >>= 1) s += __shfl_xor_sync(0xffffffffu, s, off);
        if (lane == 0) {
            float ks = kscale[row];
            g_kpar[row] = make_float4(ks, kmin[row], ks * (float)s, 0.f);
        }
    } else {
        // ---- V path ----
        float vs = vscale[row];
        int4 c = *((const int4*)(v + (size_t)row * HD) + lane);
        __half2 p0 = __floats2half2_rn(vs * (float)c.x, vs * (float)c.y);
        __half2 p1 = __floats2half2_rn(vs * (float)c.z, vs * (float)c.w);
        uint2 w; w.x = *(unsigned*)&p0; w.y = *(unsigned*)&p1;
        *((uint2*)(g_va + (size_t)row * PITCH) + lane) = w;
        if (lane == 0) {
            __half ext[8];
            ext[0] = __float2half_rn(1.0f);
            ext[1] = __float2half_rn(vmin[row]);
            #pragma unroll
            for (int i = 2; i < 8; i++) ext[i] = __float2half_rn(0.f);
            *(uint4*)(g_va + (size_t)row * PITCH + 128) = *(uint4*)ext;
        }
    }
}

__device__ __forceinline__ void cp16(uint32_t dst, const void* src) {
    asm volatile("cp.async.cg.shared.global [%0], [%1], 16;" :: "r"(dst), "l"(src));
}
__device__ __forceinline__ uint2 lds64(uint32_t a) {
    uint2 r; asm volatile("ld.shared.v2.u32 {%0,%1}, [%2];" : "=r"(r.x), "=r"(r.y) : "r"(a));
    return r;
}
__device__ __forceinline__ uint32_t smem_u32(const void* p) {
    uint32_t a;
    asm("{ .reg .u64 t; cvta.to.shared.u64 t, %1; cvt.u32.u64 %0, t; }" : "=r"(a) : "l"(p));
    return a;
}

#define MMAU8(cc, aa, b0v, b1v) \
    asm volatile("mma.sync.aligned.m16n8k32.row.col.s32.u8.u8.s32 " \
        "{%0,%1,%2,%3},{%4,%5,%6,%7},{%8,%9},{%0,%1,%2,%3};" \
        : "+r"(cc[0]), "+r"(cc[1]), "+r"(cc[2]), "+r"(cc[3]) \
        : "r"(aa[0]), "r"(aa[1]), "r"(aa[2]), "r"(aa[3]), "r"(b0v), "r"(b1v))

#define MMA16816(cc, aa, b0v, b1v) \
    asm volatile("mma.sync.aligned.m16n8k16.row.col.f32.f16.f16.f32 " \
        "{%0,%1,%2,%3},{%4,%5,%6,%7},{%8,%9},{%0,%1,%2,%3};" \
        : "+f"(cc[0]), "+f"(cc[1]), "+f"(cc[2]), "+f"(cc[3]) \
        : "r"(aa[0]), "r"(aa[1]), "r"(aa[2]), "r"(aa[3]), "r"(b0v), "r"(b1v))

// ---------------- main: flash attention, u8 QK + fp16 PV with l/b in MMA ----------------
__global__ __launch_bounds__(NTHREADS, 3) void attn_kernel(
    const int* __restrict__ qcodes,
    const float* __restrict__ qmin, const float* __restrict__ qscale,
    float* __restrict__ out)
{
    extern __shared__ __align__(16) unsigned char smem_raw[];
    const uint32_t sb = smem_u32(smem_raw);

    const int tid = threadIdx.x, warp = tid >> 5, lane = tid & 31;
    const int g = lane >> 2, tg = lane & 3;
    const int bh = blockIdx.y, q0 = blockIdx.x * BM;

    // ---- prologue: pack raw int32 Q codes -> permuted u8 smem (overlays stage-0 K),
    //      row sums + q params -> smem scratch (overlays stage-0 V) ----
    {
        const int rowp = tid >> 1, h = tid & 1;    // row 0..63, half h (kk pair 2h,2h+1)
        const int* Qg = qcodes + ((size_t)(q0 + rowp) * NBH + bh) * HD;
        int ssum = 0;
        #pragma unroll
        for (int kki = 0; kki < 2; kki++) {
            int kk = 2 * h + kki;
            unsigned wv[8];
            #pragma unroll
            for (int j = 0; j < 8; j++) {
                int4 c = *(const int4*)(Qg + kk * 32 + j * 4);
                ssum += c.x + c.y + c.z + c.w;
                unsigned packed = (unsigned)c.x | ((unsigned)c.y << 8) |
                                  ((unsigned)c.z << 16) | ((unsigned)c.w << 24);
                wv[(j < 4) ? (2 * j) : (2 * (j - 4) + 1)] = packed;
            }
            *(uint4*)(smem_raw + kk * 2048 + rowp * 32)      = make_uint4(wv[0], wv[1], wv[2], wv[3]);
            *(uint4*)(smem_raw + kk * 2048 + rowp * 32 + 16) = make_uint4(wv[4], wv[5], wv[6], wv[7]);
        }
        int osum = __shfl_xor_sync(0xffffffffu, ssum, 1);
        float qsum = (float)(ssum + osum);
        if (h == 0) {
            size_t gi = (size_t)(q0 + rowp) * NBH + bh;
            float qs = qscale[gi], qm = qmin[gi];
            *(float4*)(smem_raw + SM_V0 + rowp * 16) =
                make_float4(qs * SCLF, (qs * qsum + 128.f * qm) * SCLF, qm * SCLF, 0.f);
        }
    }
    __syncthreads();

    unsigned qf[4][4];
    const int r0 = warp * 16 + g, r1 = r0 + 8;
    #pragma unroll
    for (int kk = 0; kk < 4; kk++) {
        uint2 lo = lds64(sb + (uint32_t)(kk * 2048 + r0 * 32 + tg * 8));
        uint2 hi = lds64(sb + (uint32_t)(kk * 2048 + r1 * 32 + tg * 8));
        qf[kk][0] = lo.x; qf[kk][1] = hi.x; qf[kk][2] = lo.y; qf[kk][3] = hi.y;
    }
    const float4 qp0 = *(const float4*)(smem_raw + SM_V0 + r0 * 16);
    const float4 qp1 = *(const float4*)(smem_raw + SM_V0 + r1 * 16);
    const float qa0 = qp0.x, qB0 = qp0.y, qc0 = qp0.z;
    const float qa1 = qp1.x, qB1 = qp1.y, qc1 = qp1.z;
    __syncthreads();   // done reading Q smem + qpar scratch; stage-0 buffers may be overwritten

    // ---- cp.async tile issue ----
    auto issue_tile = [&](int kb, int st) {
        const int kbase = kb * BN;
        const uint32_t koff = st ? SM_K1 : SM_K0;
        const uint32_t voff = st ? SM_V1 : SM_V0;
        const uint32_t poff = st ? SM_P1 : SM_P0;
        const char* Kg = (const char*)g_k8 + ((size_t)kbase * NBH + bh) * 128;
        const __half* Vg = g_va + ((size_t)kbase * NBH + bh) * PITCH;
        #pragma unroll
        for (int j = 0; j < 4; j++) {
            int c = tid + j * NTHREADS;            // 0..511 ; K smem: kk*2048 + n*32 + w
            int kk = c >> 7, rem = c & 127;
            int n = rem >> 1, w = (c & 1) << 4;
            cp16(sb + koff + (uint32_t)(kk * 2048 + n * 32 + w),
                 Kg + (size_t)n * NBH * 128 + kk * 32 + w);
        }
        #pragma unroll
        for (int j = 0; j < 8; j++) {
            int chunk = tid + j * NTHREADS;        // 0..1023 : cols 0..127 (256B/row)
            int row = chunk >> 4, c16 = chunk & 15;
            cp16(sb + voff + (uint32_t)(row * PITCH + c16 * 8) * 2,
                 Vg + (size_t)row * NBH * PITCH + c16 * 8);
        }
        if (tid < 64) {
            // augmented cols 128..135 (16B tail of each row)
            cp16(sb + voff + (uint32_t)(tid * PITCH + 128) * 2,
                 Vg + (size_t)tid * NBH * PITCH + 128);
        } else {
            int key = tid - 64;
            cp16(sb + poff + key * 16, g_kpar + (size_t)(kbase + key) * NBH + bh);
        }
        asm volatile("cp.async.commit_group;" ::: "memory");
    };

    issue_tile(0, 0);

    float o[16][4], ox[4];
    #pragma unroll
    for (int i = 0; i < 16; i++) { o[i][0] = o[i][1] = o[i][2] = o[i][3] = 0.f; }
    ox[0] = ox[1] = ox[2] = ox[3] = 0.f;
    float m0 = -1e30f, m1 = -1e30f;

    for (int kb = 0; kb < SQ / BN; kb++) {
        const int st = kb & 1;
        if (kb + 1 < SQ / BN) {
            issue_tile(kb + 1, st ^ 1);
            asm volatile("cp.async.wait_group 1;" ::: "memory");
        } else {
            asm volatile("cp.async.wait_group 0;" ::: "memory");
        }
        __syncthreads();   // tile kb visible

        const uint32_t koff = st ? SM_K1 : SM_K0;
        const uint32_t voff = st ? SM_V1 : SM_V0;
        const uint32_t poff = st ? SM_P1 : SM_P0;
        const float4* sP4 = (const float4*)(smem_raw + poff);
        const uint32_t sVb = sb + voff;

        // ---- S = Q * K^T in u8 MMA (exact s32) ----
        int ci[8][4];
        #pragma unroll
        for (int i = 0; i < 8; i++) { ci[i][0] = ci[i][1] = ci[i][2] = ci[i][3] = 0; }
        const uint32_t lbase = sb + koff + (uint32_t)(g * 32 + tg * 8);
        #pragma unroll
        for (int kk = 0; kk < 4; kk++) {
            #pragma unroll
            for (int n8 = 0; n8 < 8; n8++) {
                uint2 b = lds64(lbase + (uint32_t)(kk * 2048 + n8 * 256));
                MMAU8(ci[n8], qf[kk], b.x, b.y);
            }
        }

        // ---- dequant corrections + online softmax ----
        float cf[8][4];
        float mx0 = -1e30f, mx1 = -1e30f;
        #pragma unroll
        for (int n8 = 0; n8 < 8; n8++) {
            int cc = n8 * 8 + 2 * tg;
            float4 Pa = sP4[cc], Pb = sP4[cc + 1];   // (ks, km, ks*ksum, -)
            cf[n8][0] = fmaf(qa0 * Pa.x, (float)ci[n8][0], fmaf(qB0, Pa.y, qc0 * Pa.z));
            cf[n8][1] = fmaf(qa0 * Pb.x, (float)ci[n8][1], fmaf(qB0, Pb.y, qc0 * Pb.z));
            cf[n8][2] = fmaf(qa1 * Pa.x, (float)ci[n8][2], fmaf(qB1, Pa.y, qc1 * Pa.z));
            cf[n8][3] = fmaf(qa1 * Pb.x, (float)ci[n8][3], fmaf(qB1, Pb.y, qc1 * Pb.z));
            mx0 = fmaxf(mx0, fmaxf(cf[n8][0], cf[n8][1]));
            mx1 = fmaxf(mx1, fmaxf(cf[n8][2], cf[n8][3]));
        }
        mx0 = fmaxf(mx0, __shfl_xor_sync(~0u, mx0, 1));
        mx0 = fmaxf(mx0, __shfl_xor_sync(~0u, mx0, 2));
        mx1 = fmaxf(mx1, __shfl_xor_sync(~0u, mx1, 1));
        mx1 = fmaxf(mx1, __shfl_xor_sync(~0u, mx1, 2));
        const float mn0 = fmaxf(m0, mx0), mn1 = fmaxf(m1, mx1);
        const bool nochange = (m0 == mn0) & (m1 == mn1);
        float cr0, cr1;
        asm("ex2.approx.f32 %0, %1;" : "=f"(cr0) : "f"(m0 - mn0));
        asm("ex2.approx.f32 %0, %1;" : "=f"(cr1) : "f"(m1 - mn1));
        m0 = mn0; m1 = mn1;

        // ---- p = 2^(S - m) in fp16 pairs (MUFU f16x2); becomes PV A operand directly ----
        #pragma unroll
        for (int n8 = 0; n8 < 8; n8++) {
            __half2 x0 = __floats2half2_rn(cf[n8][0] - mn0, cf[n8][1] - mn0);
            __half2 x1 = __floats2half2_rn(cf[n8][2] - mn1, cf[n8][3] - mn1);
            __half2 p0 = h2exp2(x0);
            __half2 p1 = h2exp2(x1);
            ci[n8][0] = (int)*(unsigned*)&p0;   // rows r0, keys cc..cc+1
            ci[n8][1] = (int)*(unsigned*)&p1;   // rows r1
        }
        if (!__all_sync(0xffffffffu, nochange)) {
            #pragma unroll
            for (int i = 0; i < 16; i++) {
                o[i][0] *= cr0; o[i][1] *= cr0; o[i][2] *= cr1; o[i][3] *= cr1;
            }
            ox[0] *= cr0; ox[1] *= cr0; ox[2] *= cr1; ox[3] *= cr1;
        }

        // ---- O += p * Vaug  (fp16 MMA; V via ldmatrix.trans; cols 128/129 = l/b) ----
        #pragma unroll
        for (int kk = 0; kk < 4; kk++) {
            unsigned a[4] = { (unsigned)ci[2*kk][0], (unsigned)ci[2*kk][1],
                              (unsigned)ci[2*kk + 1][0], (unsigned)ci[2*kk + 1][1] };
            #pragma unroll
            for (int nb = 0; nb < 8; nb++) {
                int rowl = kk * 16 + (lane & 15);
                int col  = nb * 16 + ((lane & 16) ? 8 : 0);
                unsigned addr = sVb + ((unsigned)(rowl * PITCH + col) << 1);
                unsigned v0, v1, v2, v3;
                asm volatile("ldmatrix.sync.aligned.m8n8.x4.trans.shared.b16 {%0,%1,%2,%3}, [%4];"
                             : "=r"(v0), "=r"(v1), "=r"(v2), "=r"(v3) : "r"(addr));
                MMA16816(o[2*nb],     a, v0, v1);
                MMA16816(o[2*nb + 1], a, v2, v3);
            }
            {   // extra n8 block: cols 128..135 (l, b, zeros)
                int rowl = kk * 16 + (lane & 15);
                unsigned addr = sVb + ((unsigned)(rowl * PITCH + 128) << 1);
                unsigned v0, v1;
                asm volatile("ldmatrix.sync.aligned.m8n8.x2.trans.shared.b16 {%0,%1}, [%2];"
                             : "=r"(v0), "=r"(v1) : "r"(addr));
                MMA16816(ox, a, v0, v1);
            }
        }
        __syncthreads();   // all reads of this stage done before refill
    }

    // ---- epilogue: l/b from MMA cols 128/129 (tg==0 lane), normalize, store fp32 ----
    const int qlead = lane & 28;
    const float l0 = __shfl_sync(0xffffffffu, ox[0], qlead);
    const float b0 = __shfl_sync(0xffffffffu, ox[1], qlead);
    const float l1 = __shfl_sync(0xffffffffu, ox[2], qlead);
    const float b1 = __shfl_sync(0xffffffffu, ox[3], qlead);
    const float iv0 = 1.f / l0, iv1 = 1.f / l1;
    float* O0 = out + (size_t)(q0 + r0) * NBH * HD + (size_t)bh * HD;
    float* O1 = out + (size_t)(q0 + r1) * NBH * HD + (size_t)bh * HD;
    #pragma unroll
    for (int i = 0; i < 16; i++) {
        int d0 = i * 8 + 2 * tg;
        float2 w0 = make_float2((o[i][0] + b0) * iv0, (o[i][1] + b0) * iv0);
        float2 w1 = make_float2((o[i][2] + b1) * iv1, (o[i][3] + b1) * iv1);
        *(float2*)(O0 + d0) = w0;
        *(float2*)(O1 + d0) = w1;
    }
}

extern "C" void kernel_launch(void* const* d_in, const int* in_sizes, int n_in,
                              void* d_out, int out_size) {
    const int*   q   = (const int*)d_in[0];
    const int*   k   = (const int*)d_in[1];
    const int*   v   = (const int*)d_in[2];
    const float* qmn = (const float*)d_in[3];
    const float* qsc = (const float*)d_in[4];
    const float* kmn = (const float*)d_in[5];
    const float* ksc = (const float*)d_in[6];
    const float* vmn = (const float*)d_in[7];
    const float* vsc = (const float*)d_in[8];

    (void)cudaFuncSetAttribute(attn_kernel, cudaFuncAttributeMaxDynamicSharedMemorySize, SMEM_BYTES);

    dim3 pg(SQ * NBH / 8, 2);   // y=0: K pack+params, y=1: V dequant+augment
    prep_kv<<<pg, 256>>>(k, v, kmn, ksc, vmn, vsc);

    dim3 ag(SQ / BM, NBH);   // qtile fastest -> concurrent CTAs share a head's K/V in L2
    attn_kernel<<<ag, NTHREADS, SMEM_BYTES>>>(q, qmn, qsc, (float*)d_out);
}

// round 15
// speedup vs baseline: 1.6201x; 1.0338x over previous
#include <cuda_runtime.h>
#include <cuda_fp16.h>
#include <cstdint>

#define SQ 2048
#define NBH 32
#define HD 128
#define BM 64            // q rows per CTA (4 warps x 16 rows)
#define BN 64
#define NTHREADS 128
#define PITCH 136        // half elements per V smem row: 128 data + [1, vm, 0..] = 272B
// smem offsets
#define SM_K0 0
#define SM_V0 8192
#define SM_K1 25600
#define SM_V1 33792
#define SM_P0 51200
#define SM_P1 52480
#define SMEM_BYTES 53760
#define SCLF 0.12752836805103852f   // log2(e)/sqrt(128)

// Persistent scratch (no cudaMalloc allowed)
__device__ unsigned g_k8[SQ*NBH*32];   // permuted u8 codes, 128B/row as 32 u32
__device__ __half g_va[(size_t)SQ*NBH*PITCH]; // augmented dequant V: [vs*code x128, 1, vm, 0 x6]
__device__ float4 g_kpar[SQ*NBH];      // (kscale, kmin, kscale*ksum, -)

// ---------------- prep: K codes -> permuted u8 + params ; V -> augmented dequant fp16 ----------------
// permuted byte order per 32-k chunk: [0-3][16-19][4-7][20-23][8-11][24-27][12-15][28-31]
__global__ void prep_kv(const int* __restrict__ k, const int* __restrict__ v,
                        const float* __restrict__ kmin, const float* __restrict__ kscale,
                        const float* __restrict__ vmin, const float* __restrict__ vscale) {
    int warp = threadIdx.x >> 5, lane = threadIdx.x & 31;
    int row = blockIdx.x * 8 + warp;               // 0 .. S*BH-1
    if (blockIdx.y == 0) {
        // ---- K path ----
        int k0 = ((lane >> 3) << 5) + ((lane & 1) << 4) + (((lane & 7) >> 1) << 2);
        int4 c = *(const int4*)(k + (size_t)row * HD + k0);
        unsigned packed = (unsigned)c.x | ((unsigned)c.y << 8) | ((unsigned)c.z << 16) | ((unsigned)c.w << 24);
        g_k8[(size_t)row * 32 + lane] = packed;
        int s = c.x + c.y + c.z + c.w;
        #pragma unroll
        for (int off = 16; off; off >>= 1) s += __shfl_xor_sync(0xffffffffu, s, off);
        if (lane == 0) {
            float ks = kscale[row];
            g_kpar[row] = make_float4(ks, kmin[row], ks * (float)s, 0.f);
        }
    } else {
        // ---- V path ----
        float vs = vscale[row];
        int4 c = *((const int4*)(v + (size_t)row * HD) + lane);
        __half2 p0 = __floats2half2_rn(vs * (float)c.x, vs * (float)c.y);
        __half2 p1 = __floats2half2_rn(vs * (float)c.z, vs * (float)c.w);
        uint2 w; w.x = *(unsigned*)&p0; w.y = *(unsigned*)&p1;
        *((uint2*)(g_va + (size_t)row * PITCH) + lane) = w;
        if (lane == 0) {
            __half ext[8];
            ext[0] = __float2half_rn(1.0f);
            ext[1] = __float2half_rn(vmin[row]);
            #pragma unroll
            for (int i = 2; i < 8; i++) ext[i] = __float2half_rn(0.f);
            *(uint4*)(g_va + (size_t)row * PITCH + 128) = *(uint4*)ext;
        }
    }
}

__device__ __forceinline__ void cp16(uint32_t dst, const void* src) {
    asm volatile("cp.async.cg.shared.global [%0], [%1], 16;" :: "r"(dst), "l"(src));
}
__device__ __forceinline__ uint2 lds64(uint32_t a) {
    uint2 r; asm volatile("ld.shared.v2.u32 {%0,%1}, [%2];" : "=r"(r.x), "=r"(r.y) : "r"(a));
    return r;
}
__device__ __forceinline__ uint32_t smem_u32(const void* p) {
    uint32_t a;
    asm("{ .reg .u64 t; cvta.to.shared.u64 t, %1; cvt.u32.u64 %0, t; }" : "=r"(a) : "l"(p));
    return a;
}

#define MMAU8(cc, aa, b0v, b1v) \
    asm volatile("mma.sync.aligned.m16n8k32.row.col.s32.u8.u8.s32 " \
        "{%0,%1,%2,%3},{%4,%5,%6,%7},{%8,%9},{%0,%1,%2,%3};" \
        : "+r"(cc[0]), "+r"(cc[1]), "+r"(cc[2]), "+r"(cc[3]) \
        : "r"(aa[0]), "r"(aa[1]), "r"(aa[2]), "r"(aa[3]), "r"(b0v), "r"(b1v))

#define MMA16816(cc, aa, b0v, b1v) \
    asm volatile("mma.sync.aligned.m16n8k16.row.col.f32.f16.f16.f32 " \
        "{%0,%1,%2,%3},{%4,%5,%6,%7},{%8,%9},{%0,%1,%2,%3};" \
        : "+f"(cc[0]), "+f"(cc[1]), "+f"(cc[2]), "+f"(cc[3]) \
        : "r"(aa[0]), "r"(aa[1]), "r"(aa[2]), "r"(aa[3]), "r"(b0v), "r"(b1v))

// ---------------- main: flash attention, u8 QK + fp16 PV with l/b in MMA ----------------
// 4 CTAs/SM: 128 regs forced (65536/(4*128)); smem 4*53760 = 215KB <= 228KB
__global__ __launch_bounds__(NTHREADS, 4) void attn_kernel(
    const int* __restrict__ qcodes,
    const float* __restrict__ qmin, const float* __restrict__ qscale,
    float* __restrict__ out)
{
    extern __shared__ __align__(16) unsigned char smem_raw[];
    const uint32_t sb = smem_u32(smem_raw);

    const int tid = threadIdx.x, warp = tid >> 5, lane = tid & 31;
    const int g = lane >> 2, tg = lane & 3;
    const int bh = blockIdx.y, q0 = blockIdx.x * BM;

    // ---- prologue: pack raw int32 Q codes -> permuted u8 smem (overlays stage-0 K),
    //      row sums + q params -> smem scratch (overlays stage-0 V) ----
    {
        const int rowp = tid >> 1, h = tid & 1;    // row 0..63, half h (kk pair 2h,2h+1)
        const int* Qg = qcodes + ((size_t)(q0 + rowp) * NBH + bh) * HD;
        int ssum = 0;
        #pragma unroll
        for (int kki = 0; kki < 2; kki++) {
            int kk = 2 * h + kki;
            unsigned wv[8];
            #pragma unroll
            for (int j = 0; j < 8; j++) {
                int4 c = *(const int4*)(Qg + kk * 32 + j * 4);
                ssum += c.x + c.y + c.z + c.w;
                unsigned packed = (unsigned)c.x | ((unsigned)c.y << 8) |
                                  ((unsigned)c.z << 16) | ((unsigned)c.w << 24);
                wv[(j < 4) ? (2 * j) : (2 * (j - 4) + 1)] = packed;
            }
            *(uint4*)(smem_raw + kk * 2048 + rowp * 32)      = make_uint4(wv[0], wv[1], wv[2], wv[3]);
            *(uint4*)(smem_raw + kk * 2048 + rowp * 32 + 16) = make_uint4(wv[4], wv[5], wv[6], wv[7]);
        }
        int osum = __shfl_xor_sync(0xffffffffu, ssum, 1);
        float qsum = (float)(ssum + osum);
        if (h == 0) {
            size_t gi = (size_t)(q0 + rowp) * NBH + bh;
            float qs = qscale[gi], qm = qmin[gi];
            *(float4*)(smem_raw + SM_V0 + rowp * 16) =
                make_float4(qs * SCLF, (qs * qsum + 128.f * qm) * SCLF, qm * SCLF, 0.f);
        }
    }
    __syncthreads();

    unsigned qf[4][4];
    const int r0 = warp * 16 + g, r1 = r0 + 8;
    #pragma unroll
    for (int kk = 0; kk < 4; kk++) {
        uint2 lo = lds64(sb + (uint32_t)(kk * 2048 + r0 * 32 + tg * 8));
        uint2 hi = lds64(sb + (uint32_t)(kk * 2048 + r1 * 32 + tg * 8));
        qf[kk][0] = lo.x; qf[kk][1] = hi.x; qf[kk][2] = lo.y; qf[kk][3] = hi.y;
    }
    const float4 qp0 = *(const float4*)(smem_raw + SM_V0 + r0 * 16);
    const float4 qp1 = *(const float4*)(smem_raw + SM_V0 + r1 * 16);
    const float qa0 = qp0.x, qB0 = qp0.y, qc0 = qp0.z;
    const float qa1 = qp1.x, qB1 = qp1.y, qc1 = qp1.z;
    __syncthreads();   // done reading Q smem + qpar scratch; stage-0 buffers may be overwritten

    // ---- cp.async tile issue ----
    auto issue_tile = [&](int kb, int st) {
        const int kbase = kb * BN;
        const uint32_t koff = st ? SM_K1 : SM_K0;
        const uint32_t voff = st ? SM_V1 : SM_V0;
        const uint32_t poff = st ? SM_P1 : SM_P0;
        const char* Kg = (const char*)g_k8 + ((size_t)kbase * NBH + bh) * 128;
        const __half* Vg = g_va + ((size_t)kbase * NBH + bh) * PITCH;
        #pragma unroll
        for (int j = 0; j < 4; j++) {
            int c = tid + j * NTHREADS;            // 0..511 ; K smem: kk*2048 + n*32 + w
            int kk = c >> 7, rem = c & 127;
            int n = rem >> 1, w = (c & 1) << 4;
            cp16(sb + koff + (uint32_t)(kk * 2048 + n * 32 + w),
                 Kg + (size_t)n * NBH * 128 + kk * 32 + w);
        }
        #pragma unroll
        for (int j = 0; j < 8; j++) {
            int chunk = tid + j * NTHREADS;        // 0..1023 : cols 0..127 (256B/row)
            int row = chunk >> 4, c16 = chunk & 15;
            cp16(sb + voff + (uint32_t)(row * PITCH + c16 * 8) * 2,
                 Vg + (size_t)row * NBH * PITCH + c16 * 8);
        }
        if (tid < 64) {
            // augmented cols 128..135 (16B tail of each row)
            cp16(sb + voff + (uint32_t)(tid * PITCH + 128) * 2,
                 Vg + (size_t)tid * NBH * PITCH + 128);
        } else {
            int key = tid - 64;
            cp16(sb + poff + key * 16, g_kpar + (size_t)(kbase + key) * NBH + bh);
        }
        asm volatile("cp.async.commit_group;" ::: "memory");
    };

    issue_tile(0, 0);

    float o[16][4], ox[4];
    #pragma unroll
    for (int i = 0; i < 16; i++) { o[i][0] = o[i][1] = o[i][2] = o[i][3] = 0.f; }
    ox[0] = ox[1] = ox[2] = ox[3] = 0.f;
    float m0 = -1e30f, m1 = -1e30f;

    for (int kb = 0; kb < SQ / BN; kb++) {
        const int st = kb & 1;
        if (kb + 1 < SQ / BN) {
            issue_tile(kb + 1, st ^ 1);
            asm volatile("cp.async.wait_group 1;" ::: "memory");
        } else {
            asm volatile("cp.async.wait_group 0;" ::: "memory");
        }
        __syncthreads();   // tile kb visible

        const uint32_t koff = st ? SM_K1 : SM_K0;
        const uint32_t voff = st ? SM_V1 : SM_V0;
        const uint32_t poff = st ? SM_P1 : SM_P0;
        const float4* sP4 = (const float4*)(smem_raw + poff);
        const uint32_t sVb = sb + voff;

        // ---- S = Q * K^T in u8 MMA (exact s32) ----
        int ci[8][4];
        #pragma unroll
        for (int i = 0; i < 8; i++) { ci[i][0] = ci[i][1] = ci[i][2] = ci[i][3] = 0; }
        const uint32_t lbase = sb + koff + (uint32_t)(g * 32 + tg * 8);
        #pragma unroll
        for (int kk = 0; kk < 4; kk++) {
            #pragma unroll
            for (int n8 = 0; n8 < 8; n8++) {
                uint2 b = lds64(lbase + (uint32_t)(kk * 2048 + n8 * 256));
                MMAU8(ci[n8], qf[kk], b.x, b.y);
            }
        }

        // ---- dequant corrections + online softmax ----
        float cf[8][4];
        float mx0 = -1e30f, mx1 = -1e30f;
        #pragma unroll
        for (int n8 = 0; n8 < 8; n8++) {
            int cc = n8 * 8 + 2 * tg;
            float4 Pa = sP4[cc], Pb = sP4[cc + 1];   // (ks, km, ks*ksum, -)
            cf[n8][0] = fmaf(qa0 * Pa.x, (float)ci[n8][0], fmaf(qB0, Pa.y, qc0 * Pa.z));
            cf[n8][1] = fmaf(qa0 * Pb.x, (float)ci[n8][1], fmaf(qB0, Pb.y, qc0 * Pb.z));
            cf[n8][2] = fmaf(qa1 * Pa.x, (float)ci[n8][2], fmaf(qB1, Pa.y, qc1 * Pa.z));
            cf[n8][3] = fmaf(qa1 * Pb.x, (float)ci[n8][3], fmaf(qB1, Pb.y, qc1 * Pb.z));
            mx0 = fmaxf(mx0, fmaxf(cf[n8][0], cf[n8][1]));
            mx1 = fmaxf(mx1, fmaxf(cf[n8][2], cf[n8][3]));
        }
        mx0 = fmaxf(mx0, __shfl_xor_sync(~0u, mx0, 1));
        mx0 = fmaxf(mx0, __shfl_xor_sync(~0u, mx0, 2));
        mx1 = fmaxf(mx1, __shfl_xor_sync(~0u, mx1, 1));
        mx1 = fmaxf(mx1, __shfl_xor_sync(~0u, mx1, 2));
        const float mn0 = fmaxf(m0, mx0), mn1 = fmaxf(m1, mx1);
        const bool nochange = (m0 == mn0) & (m1 == mn1);
        float cr0, cr1;
        asm("ex2.approx.f32 %0, %1;" : "=f"(cr0) : "f"(m0 - mn0));
        asm("ex2.approx.f32 %0, %1;" : "=f"(cr1) : "f"(m1 - mn1));
        m0 = mn0; m1 = mn1;

        // ---- p = 2^(S - m) in fp16 pairs (MUFU f16x2); becomes PV A operand directly ----
        #pragma unroll
        for (int n8 = 0; n8 < 8; n8++) {
            __half2 x0 = __floats2half2_rn(cf[n8][0] - mn0, cf[n8][1] - mn0);
            __half2 x1 = __floats2half2_rn(cf[n8][2] - mn1, cf[n8][3] - mn1);
            __half2 p0 = h2exp2(x0);
            __half2 p1 = h2exp2(x1);
            ci[n8][0] = (int)*(unsigned*)&p0;   // rows r0, keys cc..cc+1
            ci[n8][1] = (int)*(unsigned*)&p1;   // rows r1
        }
        if (!__all_sync(0xffffffffu, nochange)) {
            #pragma unroll
            for (int i = 0; i < 16; i++) {
                o[i][0] *= cr0; o[i][1] *= cr0; o[i][2] *= cr1; o[i][3] *= cr1;
            }
            ox[0] *= cr0; ox[1] *= cr0; ox[2] *= cr1; ox[3] *= cr1;
        }

        // ---- O += p * Vaug  (fp16 MMA; V via ldmatrix.trans; cols 128/129 = l/b) ----
        #pragma unroll
        for (int kk = 0; kk < 4; kk++) {
            unsigned a[4] = { (unsigned)ci[2*kk][0], (unsigned)ci[2*kk][1],
                              (unsigned)ci[2*kk + 1][0], (unsigned)ci[2*kk + 1][1] };
            #pragma unroll
            for (int nb = 0; nb < 8; nb++) {
                int rowl = kk * 16 + (lane & 15);
                int col  = nb * 16 + ((lane & 16) ? 8 : 0);
                unsigned addr = sVb + ((unsigned)(rowl * PITCH + col) << 1);
                unsigned v0, v1, v2, v3;
                asm volatile("ldmatrix.sync.aligned.m8n8.x4.trans.shared.b16 {%0,%1,%2,%3}, [%4];"
                             : "=r"(v0), "=r"(v1), "=r"(v2), "=r"(v3) : "r"(addr));
                MMA16816(o[2*nb],     a, v0, v1);
                MMA16816(o[2*nb + 1], a, v2, v3);
            }
            {   // extra n8 block: cols 128..135 (l, b, zeros)
                int rowl = kk * 16 + (lane & 15);
                unsigned addr = sVb + ((unsigned)(rowl * PITCH + 128) << 1);
                unsigned v0, v1;
                asm volatile("ldmatrix.sync.aligned.m8n8.x2.trans.shared.b16 {%0,%1}, [%2];"
                             : "=r"(v0), "=r"(v1) : "r"(addr));
                MMA16816(ox, a, v0, v1);
            }
        }
        __syncthreads();   // all reads of this stage done before refill
    }

    // ---- epilogue: l/b from MMA cols 128/129 (tg==0 lane), normalize, store fp32 ----
    const int qlead = lane & 28;
    const float l0 = __shfl_sync(0xffffffffu, ox[0], qlead);
    const float b0 = __shfl_sync(0xffffffffu, ox[1], qlead);
    const float l1 = __shfl_sync(0xffffffffu, ox[2], qlead);
    const float b1 = __shfl_sync(0xffffffffu, ox[3], qlead);
    const float iv0 = 1.f / l0, iv1 = 1.f / l1;
    float* O0 = out + (size_t)(q0 + r0) * NBH * HD + (size_t)bh * HD;
    float* O1 = out + (size_t)(q0 + r1) * NBH * HD + (size_t)bh * HD;
    #pragma unroll
    for (int i = 0; i < 16; i++) {
        int d0 = i * 8 + 2 * tg;
        float2 w0 = make_float2((o[i][0] + b0) * iv0, (o[i][1] + b0) * iv0);
        float2 w1 = make_float2((o[i][2] + b1) * iv1, (o[i][3] + b1) * iv1);
        *(float2*)(O0 + d0) = w0;
        *(float2*)(O1 + d0) = w1;
    }
}

extern "C" void kernel_launch(void* const* d_in, const int* in_sizes, int n_in,
                              void* d_out, int out_size) {
    const int*   q   = (const int*)d_in[0];
    const int*   k   = (const int*)d_in[1];
    const int*   v   = (const int*)d_in[2];
    const float* qmn = (const float*)d_in[3];
    const float* qsc = (const float*)d_in[4];
    const float* kmn = (const float*)d_in[5];
    const float* ksc = (const float*)d_in[6];
    const float* vmn = (const float*)d_in[7];
    const float* vsc = (const float*)d_in[8];

    (void)cudaFuncSetAttribute(attn_kernel, cudaFuncAttributeMaxDynamicSharedMemorySize, SMEM_BYTES);

    dim3 pg(SQ * NBH / 8, 2);   // y=0: K pack+params, y=1: V dequant+augment
    prep_kv<<<pg, 256>>>(k, v, kmn, ksc, vmn, vsc);

    dim3 ag(SQ / BM, NBH);   // qtile fastest -> concurrent CTAs share a head's K/V in L2
    attn_kernel<<<ag, NTHREADS, SMEM_BYTES>>>(q, qmn, qsc, (float*)d_out);
}